// round 1
// baseline (speedup 1.0000x reference)
#include <cuda_runtime.h>
#include <math.h>

// Problem constants
#define BB 2
#define SS 1024
#define HH 2048
#define TT (BB*SS)      // 2048 tokens
#define F1 512          // H/4
#define KD 32
#define NCACHE 16
#define CEH 64

// ---------------- scratch (static device memory; no allocations) ----------------
__device__ float g_h[TT * F1];        // scorer hidden (post-relu)   4 MB
__device__ float g_Y[TT * HH];        // layer GEMM output (+bias)  16 MB
__device__ float g_Lsel[TT * HH];     // selected low-rank update   16 MB
__device__ float g_Tsel[TT * 128];    // x @ Usel^T                  1 MB
__device__ float g_T4[TT * 4];        // x @ u4^T
__device__ float g_pooled[BB * HH];
__device__ float g_pp[8 * BB * HH];
__device__ float g_qk[BB * KD];
__device__ float g_ceh[BB * CEH];
__device__ unsigned char g_crit[TT];
__device__ unsigned char g_simp[TT];
__device__ int g_flags[4];            // [0]=best cache idx, [1]=hit, [2]=rank_idx, [3]=rank value

// ---------------- mean pool over S (two-stage, deterministic) ----------------
__global__ void pool_part(const float* __restrict__ x) {
    int i = blockIdx.x * 256 + threadIdx.x;      // over B*H = 4096
    int b = i / HH, h = i % HH;
    int c = blockIdx.y;                          // 8 chunks of 128
    const float* p = x + ((size_t)b * SS + (size_t)c * 128) * HH + h;
    float s0 = 0.f, s1 = 0.f, s2 = 0.f, s3 = 0.f;
    #pragma unroll 8
    for (int s = 0; s < 128; s += 4) {
        s0 += p[(size_t)s * HH];
        s1 += p[(size_t)(s + 1) * HH];
        s2 += p[(size_t)(s + 2) * HH];
        s3 += p[(size_t)(s + 3) * HH];
    }
    g_pp[c * BB * HH + i] = s0 + s1 + s2 + s3;
}

__global__ void pool_reduce() {
    int i = blockIdx.x * 256 + threadIdx.x;
    float s = 0.f;
    #pragma unroll
    for (int c = 0; c < 8; c++) s += g_pp[c * BB * HH + i];
    g_pooled[i] = s * (1.0f / SS);
}

// ---------------- pooled dots: qk (64 dots) + ce_h (128 dots), K=2048 ----------------
__global__ void dots_kernel(const float* __restrict__ key_proj_w,
                            const float* __restrict__ ce_w1,
                            const float* __restrict__ ce_b1) {
    int j = blockIdx.x;       // 0..191
    int tid = threadIdx.x;    // 256
    const float* pooled;
    const float* w;
    if (j < 64) {
        int b = j / KD, d = j % KD;
        pooled = g_pooled + (size_t)b * HH;
        w = key_proj_w + (size_t)d * HH;
    } else {
        int jj = j - 64;
        int b = jj / CEH, f = jj % CEH;
        pooled = g_pooled + (size_t)b * HH;
        w = ce_w1 + (size_t)f * HH;
    }
    float part = 0.f;
    for (int k = tid; k < HH; k += 256) part += pooled[k] * w[k];
    __shared__ float red[256];
    red[tid] = part;
    __syncthreads();
    for (int st = 128; st > 0; st >>= 1) {
        if (tid < st) red[tid] += red[tid + st];
        __syncthreads();
    }
    if (tid == 0) {
        float v = red[0];
        if (j < 64) {
            g_qk[j] = v;
        } else {
            int jj = j - 64;
            int f = jj % CEH;
            v += ce_b1[f];
            g_ceh[jj] = fmaxf(v, 0.f);
        }
    }
}

// ---------------- cache lookup + rank selection (1 block) ----------------
__global__ void select_kernel(const float* __restrict__ cache_keys,
                              const float* __restrict__ ce_w2,
                              const float* __restrict__ ce_b2) {
    __shared__ float qfn[64];
    __shared__ float sims[16];
    __shared__ float scores[8];
    __shared__ float qnorm;
    int tid = threadIdx.x;

    if (tid < 2) {
        float s = 0.f;
        for (int d = 0; d < KD; d++) {
            float v = g_qk[tid * KD + d];
            s += v * v;
        }
        float inv = 1.0f / fmaxf(sqrtf(s), 1e-8f);
        for (int d = 0; d < KD; d++) qfn[tid * KD + d] = g_qk[tid * KD + d] * inv;
    }
    __syncthreads();
    if (tid == 0) {
        float s = 0.f;
        for (int i = 0; i < 64; i++) s += qfn[i] * qfn[i];
        qnorm = sqrtf(s);
    }
    __syncthreads();
    if (tid < NCACHE) {
        float d = 0.f, n = 0.f;
        for (int i = 0; i < 64; i++) {
            float c = cache_keys[tid * 64 + i];
            d += c * qfn[i];
            n += c * c;
        }
        sims[tid] = d / (fmaxf(sqrtf(n), 1e-8f) * fmaxf(qnorm, 1e-8f));
    }
    if (tid < 8) {
        int b = tid / 4, r = tid % 4;
        float s = 0.f;
        for (int f = 0; f < CEH; f++) s += g_ceh[b * CEH + f] * ce_w2[r * CEH + f];
        scores[tid] = s + ce_b2[r];
    }
    __syncthreads();
    if (tid == 0) {
        int best = 0;
        float bv = sims[0];
        for (int n = 1; n < NCACHE; n++)
            if (sims[n] > bv) { bv = sims[n]; best = n; }
        g_flags[0] = best;
        g_flags[1] = (bv >= 0.95f) ? 1 : 0;
        int bi = 0;
        float sv = scores[0];
        for (int i = 1; i < 8; i++)
            if (scores[i] > sv) { sv = scores[i]; bi = i; }
        int ri = bi % 4;
        g_flags[2] = ri;
        g_flags[3] = (ri == 0) ? 4 : (ri == 1) ? 12 : (ri == 2) ? 40 : 128;
    }
}

// ---------------- tiled SGEMM body: C = A @ B^T (+bias, +relu) ----------------
// A: [M,K] lda; B: [N,K] ldb; C: [M,N] ldc. 128x64 tile, BK=16, 256 threads, 8x4/thread.
template <int EPI>   // 0 = none, 1 = +bias, 2 = +bias then relu
__device__ __forceinline__ void gemm_body(const float* __restrict__ A, int lda,
                                          const float* __restrict__ Bm, int ldb,
                                          const float* __restrict__ bias,
                                          float* __restrict__ C, int ldc,
                                          int M, int N, int K) {
    __shared__ float As[128][17];
    __shared__ float Bs[64][17];
    int bm = blockIdx.x * 128;
    int bn = blockIdx.y * 64;
    int tid = threadIdx.x;
    int tx = tid & 15;        // n group (0..15) -> 4 cols
    int ty = tid >> 4;        // m group (0..15) -> 8 rows

    float acc[8][4];
    #pragma unroll
    for (int i = 0; i < 8; i++)
        #pragma unroll
        for (int j = 0; j < 4; j++) acc[i][j] = 0.f;

    int ktiles = (K + 15) / 16;
    for (int kt = 0; kt < ktiles; kt++) {
        int k0 = kt * 16;
        // load A tile: 128x16 floats, 2 float4 per thread
        #pragma unroll
        for (int l = 0; l < 2; l++) {
            int f = tid + l * 256;
            int r = f >> 2;
            int c4 = (f & 3) * 4;
            float4 v = make_float4(0.f, 0.f, 0.f, 0.f);
            int gr = bm + r;
            if (gr < M && (k0 + c4 + 4) <= K)
                v = *(const float4*)(A + (size_t)gr * lda + k0 + c4);
            As[r][c4 + 0] = v.x; As[r][c4 + 1] = v.y;
            As[r][c4 + 2] = v.z; As[r][c4 + 3] = v.w;
        }
        // load B tile: 64x16 floats, 1 float4 per thread
        {
            int r = tid >> 2;
            int c4 = (tid & 3) * 4;
            float4 v = make_float4(0.f, 0.f, 0.f, 0.f);
            int gr = bn + r;
            if (gr < N && (k0 + c4 + 4) <= K)
                v = *(const float4*)(Bm + (size_t)gr * ldb + k0 + c4);
            Bs[r][c4 + 0] = v.x; Bs[r][c4 + 1] = v.y;
            Bs[r][c4 + 2] = v.z; Bs[r][c4 + 3] = v.w;
        }
        __syncthreads();
        #pragma unroll
        for (int kk = 0; kk < 16; kk++) {
            float a[8], b[4];
            #pragma unroll
            for (int i = 0; i < 8; i++) a[i] = As[ty * 8 + i][kk];
            #pragma unroll
            for (int j = 0; j < 4; j++) b[j] = Bs[tx * 4 + j][kk];
            #pragma unroll
            for (int i = 0; i < 8; i++)
                #pragma unroll
                for (int j = 0; j < 4; j++) acc[i][j] += a[i] * b[j];
        }
        __syncthreads();
    }
    #pragma unroll
    for (int i = 0; i < 8; i++) {
        int r = bm + ty * 8 + i;
        if (r >= M) continue;
        #pragma unroll
        for (int j = 0; j < 4; j++) {
            int c = bn + tx * 4 + j;
            if (c >= N) continue;
            float v = acc[i][j];
            if (EPI >= 1) v += bias[c];
            if (EPI == 2) v = fmaxf(v, 0.f);
            C[(size_t)r * ldc + c] = v;
        }
    }
}

template <int EPI>
__global__ __launch_bounds__(256) void gemm_k(const float* __restrict__ A,
                                              const float* __restrict__ Bm,
                                              const float* __restrict__ bias,
                                              float* __restrict__ C,
                                              int M, int N, int K) {
    gemm_body<EPI>(A, K, Bm, K, bias, C, N, M, N, K);
}

// Tsel = X @ Usel^T ; Usel picked via device flag (rank cols, rest left untouched/zero)
__global__ __launch_bounds__(256) void gemm_tsel_k(const float* __restrict__ x,
                                                   const float* __restrict__ u4,
                                                   const float* __restrict__ u12,
                                                   const float* __restrict__ u40,
                                                   const float* __restrict__ u128) {
    int ri = g_flags[2];
    int rv = g_flags[3];
    const float* U = (ri == 0) ? u4 : (ri == 1) ? u12 : (ri == 2) ? u40 : u128;
    gemm_body<0>(x, HH, U, HH, nullptr, g_Tsel, 128, TT, rv, HH);
}

// Lsel = Tsel @ Vsel^T ; Vsel is [H, rank] row-major -> B[n,k] = V[n*rank + k]
__global__ __launch_bounds__(256) void gemm_lsel_k(const float* __restrict__ v4,
                                                   const float* __restrict__ v12,
                                                   const float* __restrict__ v40,
                                                   const float* __restrict__ v128) {
    int ri = g_flags[2];
    int rv = g_flags[3];
    const float* V = (ri == 0) ? v4 : (ri == 1) ? v12 : (ri == 2) ? v40 : v128;
    gemm_body<0>(g_Tsel, 128, V, rv, nullptr, g_Lsel, HH, TT, HH, rv);
}

// ---------------- importance: content dot + sigmoid + masks (warp per token) ----------------
__global__ void imp_kernel(const float* __restrict__ w2,
                           const float* __restrict__ b2,
                           const float* __restrict__ pos) {
    int warp = threadIdx.x >> 5, lane = threadIdx.x & 31;
    int t = blockIdx.x * 8 + warp;
    float s = 0.f;
    for (int f = lane; f < F1; f += 32) s += g_h[(size_t)t * F1 + f] * w2[f];
    #pragma unroll
    for (int o = 16; o > 0; o >>= 1) s += __shfl_xor_sync(0xffffffffu, s, o);
    if (lane == 0) {
        int spos = t % SS;
        float z = s + b2[0] + 0.1f * pos[spos];
        float imp = 1.0f / (1.0f + expf(-z));
        if (spos == 0 || spos == SS - 1) imp *= 2.0f;
        g_crit[t] = (imp > 0.8f) ? 1 : 0;
        g_simp[t] = (imp < 0.3f) ? 1 : 0;
    }
}

// ---------------- T4 = X @ u4^T  (warp per token, 4 outputs) ----------------
__global__ void t4_kernel(const float* __restrict__ x, const float* __restrict__ u4) {
    int warp = threadIdx.x >> 5, lane = threadIdx.x & 31;
    int t = blockIdx.x * 8 + warp;
    float a0 = 0.f, a1 = 0.f, a2 = 0.f, a3 = 0.f;
    const float* xr = x + (size_t)t * HH;
    for (int k = lane; k < HH; k += 32) {
        float xv = xr[k];
        a0 += xv * u4[k];
        a1 += xv * u4[HH + k];
        a2 += xv * u4[2 * HH + k];
        a3 += xv * u4[3 * HH + k];
    }
    #pragma unroll
    for (int o = 16; o > 0; o >>= 1) {
        a0 += __shfl_xor_sync(0xffffffffu, a0, o);
        a1 += __shfl_xor_sync(0xffffffffu, a1, o);
        a2 += __shfl_xor_sync(0xffffffffu, a2, o);
        a3 += __shfl_xor_sync(0xffffffffu, a3, o);
    }
    if (lane == 0) {
        g_T4[t * 4 + 0] = a0;
        g_T4[t * 4 + 1] = a1;
        g_T4[t * 4 + 2] = a2;
        g_T4[t * 4 + 3] = a3;
    }
}

// ---------------- final routed epilogue (block per token) ----------------
__device__ __forceinline__ float4 f4add(float4 a, float4 b) {
    return make_float4(a.x + b.x, a.y + b.y, a.z + b.z, a.w + b.w);
}

__global__ __launch_bounds__(256) void final_kernel(const float* __restrict__ x,
                                                    const float* __restrict__ deltas,
                                                    const float* __restrict__ v4,
                                                    float* __restrict__ out) {
    int t = blockIdx.x;
    int tid = threadIdx.x;
    int crit = g_crit[t], simp = g_simp[t];
    const float4* x4 = (const float4*)(x + (size_t)t * HH);
    float4* o4 = (float4*)(out + (size_t)t * HH);

    if (crit) {
        const float4* y4 = (const float4*)(g_Y + (size_t)t * HH);
        #pragma unroll
        for (int r = 0; r < 2; r++) {
            int i = r * 256 + tid;
            o4[i] = y4[i];
        }
    } else if (simp) {
        if (g_flags[1]) {
            const float4* d4 = (const float4*)(deltas + (size_t)g_flags[0] * TT * HH + (size_t)t * HH);
            #pragma unroll
            for (int r = 0; r < 2; r++) {
                int i = r * 256 + tid;
                o4[i] = f4add(x4[i], d4[i]);
            }
        } else {
            float t0 = g_T4[t * 4 + 0], t1 = g_T4[t * 4 + 1];
            float t2 = g_T4[t * 4 + 2], t3 = g_T4[t * 4 + 3];
            const float4* v44 = (const float4*)v4;   // row h = v4[h*4 .. h*4+3]
            #pragma unroll
            for (int r = 0; r < 2; r++) {
                int i = r * 256 + tid;
                int h = i * 4;
                float4 xv = x4[i];
                float lr[4];
                #pragma unroll
                for (int j = 0; j < 4; j++) {
                    float4 vr = v44[h + j];
                    lr[j] = t0 * vr.x + t1 * vr.y + t2 * vr.z + t3 * vr.w;
                }
                o4[i] = make_float4(xv.x + lr[0], xv.y + lr[1], xv.z + lr[2], xv.w + lr[3]);
            }
        }
    } else {
        const float4* l4 = (const float4*)(g_Lsel + (size_t)t * HH);
        #pragma unroll
        for (int r = 0; r < 2; r++) {
            int i = r * 256 + tid;
            o4[i] = f4add(x4[i], l4[i]);
        }
    }
}

// ---------------- launch ----------------
extern "C" void kernel_launch(void* const* d_in, const int* in_sizes, int n_in,
                              void* d_out, int out_size) {
    const float* x          = (const float*)d_in[0];
    const float* scorer_w1  = (const float*)d_in[1];
    const float* scorer_b1  = (const float*)d_in[2];
    const float* scorer_w2  = (const float*)d_in[3];
    const float* scorer_b2  = (const float*)d_in[4];
    const float* pos_imp    = (const float*)d_in[5];
    const float* key_proj_w = (const float*)d_in[6];
    const float* cache_keys = (const float*)d_in[7];
    const float* cache_del  = (const float*)d_in[8];
    const float* ce_w1      = (const float*)d_in[9];
    const float* ce_b1      = (const float*)d_in[10];
    const float* ce_w2      = (const float*)d_in[11];
    const float* ce_b2      = (const float*)d_in[12];
    const float* u4   = (const float*)d_in[13];
    const float* v4   = (const float*)d_in[14];
    const float* u12  = (const float*)d_in[15];
    const float* v12  = (const float*)d_in[16];
    const float* u40  = (const float*)d_in[17];
    const float* v40  = (const float*)d_in[18];
    const float* u128 = (const float*)d_in[19];
    const float* v128 = (const float*)d_in[20];
    const float* layer_w = (const float*)d_in[21];
    const float* layer_b = (const float*)d_in[22];
    float* out = (float*)d_out;

    float* d_gh;    cudaGetSymbolAddress((void**)&d_gh, g_h);
    float* d_gY;    cudaGetSymbolAddress((void**)&d_gY, g_Y);

    // 1) pooled mean over S
    pool_part<<<dim3(16, 8), 256>>>(x);
    pool_reduce<<<16, 256>>>();
    // 2) pooled dots (qk + ce hidden)
    dots_kernel<<<192, 256>>>(key_proj_w, ce_w1, ce_b1);
    // 3) cache-sim argmax + rank selection -> g_flags
    select_kernel<<<1, 128>>>(cache_keys, ce_w2, ce_b2);
    // 4) scorer GEMM: g_h = relu(X @ w1^T + b1)   [2048 x 512]
    gemm_k<2><<<dim3(16, 8), 256>>>(x, scorer_w1, scorer_b1, d_gh, TT, F1, HH);
    // 5) importance + masks
    imp_kernel<<<256, 256>>>(scorer_w2, scorer_b2, pos_imp);
    // 6) layer GEMM: g_Y = X @ layer_w^T + layer_b   [2048 x 2048]
    gemm_k<1><<<dim3(16, 32), 256>>>(x, layer_w, layer_b, d_gY, TT, HH, HH);
    // 7) T4 = X @ u4^T (always needed for simple-miss path)
    t4_kernel<<<256, 256>>>(x, u4);
    // 8) Tsel = X @ Usel^T (rank from device flags)
    gemm_tsel_k<<<dim3(16, 2), 256>>>(x, u4, u12, u40, u128);
    // 9) Lsel = Tsel @ Vsel^T
    gemm_lsel_k<<<dim3(16, 32), 256>>>(v4, v12, v40, v128);
    // 10) route per token
    final_kernel<<<TT, 256>>>(x, cache_del, v4, out);
}

// round 4
// speedup vs baseline: 2.7483x; 2.7483x over previous
#include <cuda_runtime.h>
#include <cstdint>
#include <math.h>

// Problem constants
#define BB 2
#define SS 1024
#define HH 2048
#define TT (BB*SS)      // 2048 tokens
#define F1 512          // H/4
#define KD 32
#define NCACHE 16
#define CEH 64

// ---------------- scratch (static device memory; no allocations) ----------------
__device__ float g_hP[2 * TT * F1];   // scorer split-K partials (2 x 4MB)
__device__ float g_Y[TT * HH];        // layer GEMM output, compacted critical rows
__device__ float g_Lsel[TT * HH];     // low-rank update, compacted normal rows
__device__ float g_Tsel[TT * 128];    // compacted normal rows @ Usel^T
__device__ float g_TselP[8 * TT * 128]; // Tsel split-K partials
__device__ float g_T4[TT * 4];
__device__ float g_pooled[BB * HH];
__device__ float g_pp[8 * BB * HH];
__device__ float g_qk[BB * KD];
__device__ float g_ceh[BB * CEH];
__device__ unsigned char g_crit[TT];
__device__ unsigned char g_simp[TT];
__device__ int g_cidx[TT];            // critical token indices (compacted)
__device__ int g_nidx[TT];            // normal token indices (compacted)
__device__ int g_pos[TT];             // token -> compact position
__device__ int g_cnt[2];              // [0]=n_critical, [1]=n_normal
__device__ int g_flags[4];            // [0]=best cache idx, [1]=hit, [2]=rank_idx, [3]=rank

// =================== tf32 helpers ===================
__device__ __forceinline__ void f2tf32x2(float x, uint32_t& hi, uint32_t& lo) {
    asm("cvt.rna.tf32.f32 %0, %1;" : "=r"(hi) : "f"(x));
    float r = x - __uint_as_float(hi);
    asm("cvt.rna.tf32.f32 %0, %1;" : "=r"(lo) : "f"(r));
}

#define MMA8(c, a0, a1, a2, a3, b0, b1) \
    asm volatile("mma.sync.aligned.m16n8k8.row.col.f32.tf32.tf32.f32 " \
                 "{%0,%1,%2,%3},{%4,%5,%6,%7},{%8,%9},{%0,%1,%2,%3};" \
                 : "+f"((c)[0]), "+f"((c)[1]), "+f"((c)[2]), "+f"((c)[3]) \
                 : "r"(a0), "r"(a1), "r"(a2), "r"(a3), "r"(b0), "r"(b1))

// =================== mma.sync 3xTF32 GEMM: C = A @ B^T ===================
// CTA tile 128(M) x 128(N), BK=32, 256 threads = 8 warps (4 M x 2 N),
// warp tile 32x64 = 2x8 m16n8k8 tiles. A rows optionally gathered via aidx;
// dynamic M via mcnt. B rows >= Nb and k >= K are zero-filled.
#define LDP 36                      // padded row stride (uint32) for smem tiles
#define SMEM_GEMM (4 * 128 * LDP * 4)   // AHI, ALO, BHI, BLO

template <int EPI>   // 0 none, 1 +bias
__device__ void mma_gemm_body(const float* __restrict__ A, int lda,
                              const int* __restrict__ aidx,
                              const int* __restrict__ mcnt, int Mstat,
                              const float* __restrict__ B, int ldb, int Nb,
                              const float* __restrict__ bias,
                              float* __restrict__ C, int ldc, int Ncols,
                              int K, int kt_begin, int kt_end) {
    extern __shared__ uint32_t smem_u[];
    uint32_t* AHI = smem_u;
    uint32_t* ALO = smem_u + 128 * LDP;
    uint32_t* BHI = smem_u + 2 * 128 * LDP;
    uint32_t* BLO = smem_u + 3 * 128 * LDP;

    int M = mcnt ? *mcnt : Mstat;
    int bm = blockIdx.x * 128, bn = blockIdx.y * 128;
    if (bm >= M) return;

    int tid = threadIdx.x, wid = tid >> 5, lane = tid & 31;
    int wm = wid & 3, wn = wid >> 2;
    int group = lane >> 2, tg = lane & 3;

    // per-thread loader slots (4 each for A and B): row, kc fixed across kt
    const float* apt[4];
    const float* bpt[4];
    int rowv[4], kcv[4];
    #pragma unroll
    for (int i = 0; i < 4; i++) {
        int f = tid + i * 256;
        int row = f >> 3, kc = (f & 7) * 4;
        rowv[i] = row; kcv[i] = kc;
        int ar = bm + row;
        apt[i] = (ar < M) ? (A + (size_t)(aidx ? aidx[ar] : ar) * lda + kc) : nullptr;
        int br = bn + row;
        bpt[i] = (br < Nb) ? (B + (size_t)br * ldb + kc) : nullptr;
    }

    float acc[2][8][4];
    #pragma unroll
    for (int mi = 0; mi < 2; mi++)
        #pragma unroll
        for (int ni = 0; ni < 8; ni++)
            #pragma unroll
            for (int q = 0; q < 4; q++) acc[mi][ni][q] = 0.f;

    float4 ra[4], rb[4];
    // prefetch first tile
    {
        int k0 = kt_begin * 32;
        #pragma unroll
        for (int i = 0; i < 4; i++) {
            int gk = k0 + kcv[i];
            float4 z = make_float4(0.f, 0.f, 0.f, 0.f);
            ra[i] = (apt[i] && gk < K) ? *(const float4*)(apt[i] + k0) : z;
            rb[i] = (bpt[i] && gk < K) ? *(const float4*)(bpt[i] + k0) : z;
        }
    }

    for (int kt = kt_begin; kt < kt_end; kt++) {
        __syncthreads();   // previous compute done; smem reusable
        #pragma unroll
        for (int i = 0; i < 4; i++) {
            int off = rowv[i] * LDP + kcv[i];
            uint4 h, l;
            f2tf32x2(ra[i].x, h.x, l.x); f2tf32x2(ra[i].y, h.y, l.y);
            f2tf32x2(ra[i].z, h.z, l.z); f2tf32x2(ra[i].w, h.w, l.w);
            *(uint4*)(AHI + off) = h;
            *(uint4*)(ALO + off) = l;
            f2tf32x2(rb[i].x, h.x, l.x); f2tf32x2(rb[i].y, h.y, l.y);
            f2tf32x2(rb[i].z, h.z, l.z); f2tf32x2(rb[i].w, h.w, l.w);
            *(uint4*)(BHI + off) = h;
            *(uint4*)(BLO + off) = l;
        }
        __syncthreads();   // tile visible

        if (kt + 1 < kt_end) {
            int k0 = (kt + 1) * 32;
            #pragma unroll
            for (int i = 0; i < 4; i++) {
                int gk = k0 + kcv[i];
                float4 z = make_float4(0.f, 0.f, 0.f, 0.f);
                ra[i] = (apt[i] && gk < K) ? *(const float4*)(apt[i] + k0) : z;
                rb[i] = (bpt[i] && gk < K) ? *(const float4*)(bpt[i] + k0) : z;
            }
        }

        #pragma unroll
        for (int ks = 0; ks < 4; ks++) {
            int kb = ks * 8 + tg;
            uint32_t ah[2][4], al[2][4];
            #pragma unroll
            for (int mi = 0; mi < 2; mi++) {
                int r0 = (wm * 32 + mi * 16 + group) * LDP;
                ah[mi][0] = AHI[r0 + kb];
                ah[mi][1] = AHI[r0 + 8 * LDP + kb];
                ah[mi][2] = AHI[r0 + kb + 4];
                ah[mi][3] = AHI[r0 + 8 * LDP + kb + 4];
                al[mi][0] = ALO[r0 + kb];
                al[mi][1] = ALO[r0 + 8 * LDP + kb];
                al[mi][2] = ALO[r0 + kb + 4];
                al[mi][3] = ALO[r0 + 8 * LDP + kb + 4];
            }
            #pragma unroll
            for (int ni = 0; ni < 8; ni++) {
                int nr = (wn * 64 + ni * 8 + group) * LDP;
                uint32_t bh0 = BHI[nr + kb], bh1 = BHI[nr + kb + 4];
                uint32_t bl0 = BLO[nr + kb], bl1 = BLO[nr + kb + 4];
                #pragma unroll
                for (int mi = 0; mi < 2; mi++) {
                    MMA8(acc[mi][ni], ah[mi][0], ah[mi][1], ah[mi][2], ah[mi][3], bh0, bh1);
                    MMA8(acc[mi][ni], ah[mi][0], ah[mi][1], ah[mi][2], ah[mi][3], bl0, bl1);
                    MMA8(acc[mi][ni], al[mi][0], al[mi][1], al[mi][2], al[mi][3], bh0, bh1);
                }
            }
        }
    }

    // epilogue: C rows are compact indices (no gather on store)
    #pragma unroll
    for (int mi = 0; mi < 2; mi++) {
        int r0 = bm + wm * 32 + mi * 16 + group;
        #pragma unroll
        for (int ni = 0; ni < 8; ni++) {
            int col = bn + wn * 64 + ni * 8 + 2 * tg;
            if (col >= Ncols) continue;
            float b0 = 0.f, b1 = 0.f;
            if (EPI == 1) { b0 = bias[col]; b1 = bias[col + 1]; }
            if (r0 < M) {
                float2 v = make_float2(acc[mi][ni][0] + b0, acc[mi][ni][1] + b1);
                *(float2*)(C + (size_t)r0 * ldc + col) = v;
            }
            if (r0 + 8 < M) {
                float2 v = make_float2(acc[mi][ni][2] + b0, acc[mi][ni][3] + b1);
                *(float2*)(C + (size_t)(r0 + 8) * ldc + col) = v;
            }
        }
    }
}

template <int EPI>
__global__ __launch_bounds__(256, 1) void g_gemm(const float* A, int lda,
                                                 const int* aidx, const int* mcnt, int Mstat,
                                                 const float* B, int ldb, int Nb,
                                                 const float* bias,
                                                 float* C, int ldc, int Ncols,
                                                 int K, int splits, size_t cstride) {
    int nkt = (K + 31) / 32;
    int per = nkt / splits;
    int z = blockIdx.z;
    mma_gemm_body<EPI>(A, lda, aidx, mcnt, Mstat, B, ldb, Nb, bias,
                       C + (size_t)z * cstride, ldc, Ncols, K,
                       z * per, (z + 1 == splits) ? nkt : (z + 1) * per);
}

// Tsel partials: compact normal rows of x @ Usel^T, split-K x8
__global__ __launch_bounds__(256, 1) void g_tsel(const float* x,
                                                 const float* u4, const float* u12,
                                                 const float* u40, const float* u128) {
    int ri = g_flags[2], rv = g_flags[3];
    const float* U = (ri == 0) ? u4 : (ri == 1) ? u12 : (ri == 2) ? u40 : u128;
    int z = blockIdx.z;
    mma_gemm_body<0>(x, HH, g_nidx, &g_cnt[1], 0, U, HH, rv, nullptr,
                     g_TselP + (size_t)z * TT * 128, 128, 128, HH, z * 8, z * 8 + 8);
}

__global__ void tsel_reduce() {
    int n = g_cnt[1] * 128;
    int i = blockIdx.x * 256 + threadIdx.x;
    if (i >= n) return;
    float s = 0.f;
    #pragma unroll
    for (int z = 0; z < 8; z++) s += g_TselP[(size_t)z * TT * 128 + i];
    g_Tsel[i] = s;
}

// Lsel: compact Tsel rows @ Vsel^T  (K = rank, dynamic)
__global__ __launch_bounds__(256, 1) void g_lsel(const float* v4, const float* v12,
                                                 const float* v40, const float* v128) {
    int ri = g_flags[2], rv = g_flags[3];
    const float* V = (ri == 0) ? v4 : (ri == 1) ? v12 : (ri == 2) ? v40 : v128;
    mma_gemm_body<0>(g_Tsel, 128, nullptr, &g_cnt[1], 0, V, rv, HH, nullptr,
                     g_Lsel, HH, HH, rv, 0, (rv + 31) / 32);
}

// =================== small kernels ===================
__global__ void pool_part(const float* __restrict__ x) {
    int i = blockIdx.x * 256 + threadIdx.x;
    int b = i / HH, h = i % HH;
    int c = blockIdx.y;
    const float* p = x + ((size_t)b * SS + (size_t)c * 128) * HH + h;
    float s0 = 0.f, s1 = 0.f, s2 = 0.f, s3 = 0.f;
    #pragma unroll 8
    for (int s = 0; s < 128; s += 4) {
        s0 += p[(size_t)s * HH];
        s1 += p[(size_t)(s + 1) * HH];
        s2 += p[(size_t)(s + 2) * HH];
        s3 += p[(size_t)(s + 3) * HH];
    }
    g_pp[c * BB * HH + i] = s0 + s1 + s2 + s3;
}

__global__ void pool_reduce() {
    int i = blockIdx.x * 256 + threadIdx.x;
    float s = 0.f;
    #pragma unroll
    for (int c = 0; c < 8; c++) s += g_pp[c * BB * HH + i];
    g_pooled[i] = s * (1.0f / SS);
}

__global__ void dots_kernel(const float* __restrict__ key_proj_w,
                            const float* __restrict__ ce_w1,
                            const float* __restrict__ ce_b1) {
    int j = blockIdx.x;
    int tid = threadIdx.x;
    const float* pooled;
    const float* w;
    if (j < 64) {
        int b = j / KD, d = j % KD;
        pooled = g_pooled + (size_t)b * HH;
        w = key_proj_w + (size_t)d * HH;
    } else {
        int jj = j - 64;
        int b = jj / CEH, f = jj % CEH;
        pooled = g_pooled + (size_t)b * HH;
        w = ce_w1 + (size_t)f * HH;
    }
    float part = 0.f;
    for (int k = tid; k < HH; k += 256) part += pooled[k] * w[k];
    __shared__ float red[256];
    red[tid] = part;
    __syncthreads();
    for (int st = 128; st > 0; st >>= 1) {
        if (tid < st) red[tid] += red[tid + st];
        __syncthreads();
    }
    if (tid == 0) {
        float v = red[0];
        if (j < 64) {
            g_qk[j] = v;
        } else {
            int jj = j - 64;
            int f = jj % CEH;
            v += ce_b1[f];
            g_ceh[jj] = fmaxf(v, 0.f);
        }
    }
}

__global__ void select_kernel(const float* __restrict__ cache_keys,
                              const float* __restrict__ ce_w2,
                              const float* __restrict__ ce_b2) {
    __shared__ float qfn[64];
    __shared__ float sims[16];
    __shared__ float scores[8];
    __shared__ float qnorm;
    int tid = threadIdx.x;

    if (tid < 2) {
        float s = 0.f;
        for (int d = 0; d < KD; d++) {
            float v = g_qk[tid * KD + d];
            s += v * v;
        }
        float inv = 1.0f / fmaxf(sqrtf(s), 1e-8f);
        for (int d = 0; d < KD; d++) qfn[tid * KD + d] = g_qk[tid * KD + d] * inv;
    }
    __syncthreads();
    if (tid == 0) {
        float s = 0.f;
        for (int i = 0; i < 64; i++) s += qfn[i] * qfn[i];
        qnorm = sqrtf(s);
    }
    __syncthreads();
    if (tid < NCACHE) {
        float d = 0.f, n = 0.f;
        for (int i = 0; i < 64; i++) {
            float c = cache_keys[tid * 64 + i];
            d += c * qfn[i];
            n += c * c;
        }
        sims[tid] = d / (fmaxf(sqrtf(n), 1e-8f) * fmaxf(qnorm, 1e-8f));
    }
    if (tid < 8) {
        int b = tid / 4, r = tid % 4;
        float s = 0.f;
        for (int f = 0; f < CEH; f++) s += g_ceh[b * CEH + f] * ce_w2[r * CEH + f];
        scores[tid] = s + ce_b2[r];
    }
    __syncthreads();
    if (tid == 0) {
        int best = 0;
        float bv = sims[0];
        for (int n = 1; n < NCACHE; n++)
            if (sims[n] > bv) { bv = sims[n]; best = n; }
        g_flags[0] = best;
        g_flags[1] = (bv >= 0.95f) ? 1 : 0;
        int bi = 0;
        float sv = scores[0];
        for (int i = 1; i < 8; i++)
            if (scores[i] > sv) { sv = scores[i]; bi = i; }
        int ri = bi % 4;
        g_flags[2] = ri;
        g_flags[3] = (ri == 0) ? 4 : (ri == 1) ? 12 : (ri == 2) ? 40 : 128;
    }
}

// importance from scorer split-K partials (fused bias+relu+dot), warp per token
__global__ void imp_kernel(const float* __restrict__ w2,
                           const float* __restrict__ b2,
                           const float* __restrict__ b1,
                           const float* __restrict__ pos) {
    int warp = threadIdx.x >> 5, lane = threadIdx.x & 31;
    int t = blockIdx.x * 8 + warp;
    float s = 0.f;
    const float* p0 = g_hP + (size_t)t * F1;
    const float* p1 = g_hP + (size_t)TT * F1 + (size_t)t * F1;
    for (int f = lane; f < F1; f += 32) {
        float h = fmaxf(p0[f] + p1[f] + b1[f], 0.f);
        s += h * w2[f];
    }
    #pragma unroll
    for (int o = 16; o > 0; o >>= 1) s += __shfl_xor_sync(0xffffffffu, s, o);
    if (lane == 0) {
        int spos = t % SS;
        float z = s + b2[0] + 0.1f * pos[spos];
        float imp = 1.0f / (1.0f + expf(-z));
        if (spos == 0 || spos == SS - 1) imp *= 2.0f;
        g_crit[t] = (imp > 0.8f) ? 1 : 0;
        g_simp[t] = (imp < 0.3f) ? 1 : 0;
    }
}

// single-warp deterministic compaction
__global__ void compact_kernel() {
    int lane = threadIdx.x;
    int cb = 0, nb = 0;
    for (int it = 0; it < TT / 32; it++) {
        int t = it * 32 + lane;
        int c = g_crit[t], s = g_simp[t];
        int nn = !(c || s);
        unsigned cm = __ballot_sync(0xffffffffu, c);
        unsigned nm = __ballot_sync(0xffffffffu, nn);
        unsigned lt = (1u << lane) - 1u;
        if (c) { int p = cb + __popc(cm & lt); g_cidx[p] = t; g_pos[t] = p; }
        if (nn) { int p = nb + __popc(nm & lt); g_nidx[p] = t; g_pos[t] = p; }
        cb += __popc(cm);
        nb += __popc(nm);
    }
    if (lane == 0) { g_cnt[0] = cb; g_cnt[1] = nb; }
}

__global__ void t4_kernel(const float* __restrict__ x, const float* __restrict__ u4) {
    int warp = threadIdx.x >> 5, lane = threadIdx.x & 31;
    int t = blockIdx.x * 8 + warp;
    float a0 = 0.f, a1 = 0.f, a2 = 0.f, a3 = 0.f;
    const float* xr = x + (size_t)t * HH;
    for (int k = lane; k < HH; k += 32) {
        float xv = xr[k];
        a0 += xv * u4[k];
        a1 += xv * u4[HH + k];
        a2 += xv * u4[2 * HH + k];
        a3 += xv * u4[3 * HH + k];
    }
    #pragma unroll
    for (int o = 16; o > 0; o >>= 1) {
        a0 += __shfl_xor_sync(0xffffffffu, a0, o);
        a1 += __shfl_xor_sync(0xffffffffu, a1, o);
        a2 += __shfl_xor_sync(0xffffffffu, a2, o);
        a3 += __shfl_xor_sync(0xffffffffu, a3, o);
    }
    if (lane == 0) {
        g_T4[t * 4 + 0] = a0;
        g_T4[t * 4 + 1] = a1;
        g_T4[t * 4 + 2] = a2;
        g_T4[t * 4 + 3] = a3;
    }
}

__device__ __forceinline__ float4 f4add(float4 a, float4 b) {
    return make_float4(a.x + b.x, a.y + b.y, a.z + b.z, a.w + b.w);
}

__global__ __launch_bounds__(256) void final_kernel(const float* __restrict__ x,
                                                    const float* __restrict__ deltas,
                                                    const float* __restrict__ v4,
                                                    float* __restrict__ out) {
    int t = blockIdx.x;
    int tid = threadIdx.x;
    int crit = g_crit[t], simp = g_simp[t];
    const float4* x4 = (const float4*)(x + (size_t)t * HH);
    float4* o4 = (float4*)(out + (size_t)t * HH);

    if (crit) {
        const float4* y4 = (const float4*)(g_Y + (size_t)g_pos[t] * HH);
        #pragma unroll
        for (int r = 0; r < 2; r++) {
            int i = r * 256 + tid;
            o4[i] = y4[i];
        }
    } else if (simp) {
        if (g_flags[1]) {
            const float4* d4 = (const float4*)(deltas + (size_t)g_flags[0] * TT * HH + (size_t)t * HH);
            #pragma unroll
            for (int r = 0; r < 2; r++) {
                int i = r * 256 + tid;
                o4[i] = f4add(x4[i], d4[i]);
            }
        } else {
            float t0 = g_T4[t * 4 + 0], t1 = g_T4[t * 4 + 1];
            float t2 = g_T4[t * 4 + 2], t3 = g_T4[t * 4 + 3];
            const float4* v44 = (const float4*)v4;
            #pragma unroll
            for (int r = 0; r < 2; r++) {
                int i = r * 256 + tid;
                int h = i * 4;
                float4 xv = x4[i];
                float lr[4];
                #pragma unroll
                for (int j = 0; j < 4; j++) {
                    float4 vr = v44[h + j];
                    lr[j] = t0 * vr.x + t1 * vr.y + t2 * vr.z + t3 * vr.w;
                }
                o4[i] = make_float4(xv.x + lr[0], xv.y + lr[1], xv.z + lr[2], xv.w + lr[3]);
            }
        }
    } else {
        const float4* l4 = (const float4*)(g_Lsel + (size_t)g_pos[t] * HH);
        #pragma unroll
        for (int r = 0; r < 2; r++) {
            int i = r * 256 + tid;
            o4[i] = f4add(x4[i], l4[i]);
        }
    }
}

// =================== launch ===================
extern "C" void kernel_launch(void* const* d_in, const int* in_sizes, int n_in,
                              void* d_out, int out_size) {
    const float* x          = (const float*)d_in[0];
    const float* scorer_w1  = (const float*)d_in[1];
    const float* scorer_b1  = (const float*)d_in[2];
    const float* scorer_w2  = (const float*)d_in[3];
    const float* scorer_b2  = (const float*)d_in[4];
    const float* pos_imp    = (const float*)d_in[5];
    const float* key_proj_w = (const float*)d_in[6];
    const float* cache_keys = (const float*)d_in[7];
    const float* cache_del  = (const float*)d_in[8];
    const float* ce_w1      = (const float*)d_in[9];
    const float* ce_b1      = (const float*)d_in[10];
    const float* ce_w2      = (const float*)d_in[11];
    const float* ce_b2      = (const float*)d_in[12];
    const float* u4   = (const float*)d_in[13];
    const float* v4   = (const float*)d_in[14];
    const float* u12  = (const float*)d_in[15];
    const float* v12  = (const float*)d_in[16];
    const float* u40  = (const float*)d_in[17];
    const float* v40  = (const float*)d_in[18];
    const float* u128 = (const float*)d_in[19];
    const float* v128 = (const float*)d_in[20];
    const float* layer_w = (const float*)d_in[21];
    const float* layer_b = (const float*)d_in[22];
    float* out = (float*)d_out;

    float* d_hP;  cudaGetSymbolAddress((void**)&d_hP, g_hP);
    float* d_Y;   cudaGetSymbolAddress((void**)&d_Y, g_Y);
    int*   d_cidx; cudaGetSymbolAddress((void**)&d_cidx, g_cidx);
    int*   d_cnt;  cudaGetSymbolAddress((void**)&d_cnt, g_cnt);

    cudaFuncSetAttribute(g_gemm<0>, cudaFuncAttributeMaxDynamicSharedMemorySize, SMEM_GEMM);
    cudaFuncSetAttribute(g_gemm<1>, cudaFuncAttributeMaxDynamicSharedMemorySize, SMEM_GEMM);
    cudaFuncSetAttribute(g_tsel,    cudaFuncAttributeMaxDynamicSharedMemorySize, SMEM_GEMM);
    cudaFuncSetAttribute(g_lsel,    cudaFuncAttributeMaxDynamicSharedMemorySize, SMEM_GEMM);

    // 1) pooled mean over S
    pool_part<<<dim3(16, 8), 256>>>(x);
    pool_reduce<<<16, 256>>>();
    // 2) pooled dots + selection flags
    dots_kernel<<<192, 256>>>(key_proj_w, ce_w1, ce_b1);
    select_kernel<<<1, 128>>>(cache_keys, ce_w2, ce_b2);
    // 3) scorer GEMM, split-K x2 (partials; bias+relu fused into imp)
    g_gemm<0><<<dim3(16, 4, 2), 256, SMEM_GEMM>>>(x, HH, nullptr, nullptr, TT,
                                                  scorer_w1, HH, F1, nullptr,
                                                  d_hP, F1, F1, HH, 2, (size_t)TT * F1);
    // 4) importance + masks
    imp_kernel<<<256, 256>>>(scorer_w2, scorer_b2, scorer_b1, pos_imp);
    // 5) compaction
    compact_kernel<<<1, 32>>>();
    // 6) layer GEMM on critical tokens only
    g_gemm<1><<<dim3(16, 16, 1), 256, SMEM_GEMM>>>(x, HH, d_cidx, d_cnt, 0,
                                                   layer_w, HH, HH, layer_b,
                                                   d_Y, HH, HH, HH, 1, 0);
    // 7) T4 (simple-miss path, all tokens — tiny)
    t4_kernel<<<256, 256>>>(x, u4);
    // 8) Tsel on normal tokens, split-K x8, then reduce
    g_tsel<<<dim3(16, 1, 8), 256, SMEM_GEMM>>>(x, u4, u12, u40, u128);
    tsel_reduce<<<TT * 128 / 256, 256>>>();
    // 9) Lsel on normal tokens
    g_lsel<<<dim3(16, 16, 1), 256, SMEM_GEMM>>>(v4, v12, v40, v128);
    // 10) route per token
    final_kernel<<<TT, 256>>>(x, cache_del, v4, out);
}

// round 5
// speedup vs baseline: 3.7044x; 1.3479x over previous
#include <cuda_runtime.h>
#include <cuda_bf16.h>
#include <cstdint>
#include <math.h>

// Problem constants
#define BB 2
#define SS 1024
#define HH 2048
#define TT (BB*SS)      // 2048 tokens
#define F1 512          // H/4
#define KD 32
#define NCACHE 16
#define CEH 64

// ---------------- scratch (static device memory; no allocations) ----------------
__device__ float g_hP[2 * TT * F1];
__device__ float g_Y[TT * HH];
__device__ float g_Lsel[TT * HH];
__device__ float g_Tsel[TT * 128];
__device__ float g_TselP[8 * TT * 128];
__device__ float g_T4[TT * 4];
__device__ float g_pooled[BB * HH];
__device__ float g_pp[8 * BB * HH];
__device__ float g_qk[BB * KD];
__device__ float g_ceh[BB * CEH];
__device__ unsigned char g_crit[TT];
__device__ unsigned char g_simp[TT];
__device__ int g_cidx[TT];
__device__ int g_nidx[TT];
__device__ int g_pos[TT];
__device__ int g_cnt[2];
__device__ int g_flags[4];

// =================== conversion helpers ===================
__device__ __forceinline__ void f2tf32x2(float x, uint32_t& hi, uint32_t& lo) {
    asm("cvt.rna.tf32.f32 %0, %1;" : "=r"(hi) : "f"(x));
    float r = x - __uint_as_float(hi);
    asm("cvt.rna.tf32.f32 %0, %1;" : "=r"(lo) : "f"(r));
}

__device__ __forceinline__ void f2bf2(float x, float y, uint32_t& hi, uint32_t& lo) {
    __nv_bfloat162 h = __floats2bfloat162_rn(x, y);
    float rx = x - __bfloat162float(h.x);
    float ry = y - __bfloat162float(h.y);
    __nv_bfloat162 l = __floats2bfloat162_rn(rx, ry);
    hi = *(uint32_t*)&h;
    lo = *(uint32_t*)&l;
}

#define MMA8(c, a0, a1, a2, a3, b0, b1) \
    asm volatile("mma.sync.aligned.m16n8k8.row.col.f32.tf32.tf32.f32 " \
                 "{%0,%1,%2,%3},{%4,%5,%6,%7},{%8,%9},{%0,%1,%2,%3};" \
                 : "+f"((c)[0]), "+f"((c)[1]), "+f"((c)[2]), "+f"((c)[3]) \
                 : "r"(a0), "r"(a1), "r"(a2), "r"(a3), "r"(b0), "r"(b1))

#define MMA16(c, a0, a1, a2, a3, b0, b1) \
    asm volatile("mma.sync.aligned.m16n8k16.row.col.f32.bf16.bf16.f32 " \
                 "{%0,%1,%2,%3},{%4,%5,%6,%7},{%8,%9},{%0,%1,%2,%3};" \
                 : "+f"((c)[0]), "+f"((c)[1]), "+f"((c)[2]), "+f"((c)[3]) \
                 : "r"(a0), "r"(a1), "r"(a2), "r"(a3), "r"(b0), "r"(b1))

// =================== tf32 3x GEMM (scorer only): C = A @ B^T ===================
#define LDP 36
#define SMEM_TF (4 * 128 * LDP * 4)

__device__ void tf32_gemm_body(const float* __restrict__ A, int lda,
                               const float* __restrict__ B, int ldb, int Nb,
                               float* __restrict__ C, int ldc, int Ncols,
                               int K, int kt_begin, int kt_end) {
    extern __shared__ uint32_t smem_u[];
    uint32_t* AHI = smem_u;
    uint32_t* ALO = smem_u + 128 * LDP;
    uint32_t* BHI = smem_u + 2 * 128 * LDP;
    uint32_t* BLO = smem_u + 3 * 128 * LDP;

    int bm = blockIdx.x * 128, bn = blockIdx.y * 128;
    int tid = threadIdx.x, wid = tid >> 5, lane = tid & 31;
    int wm = wid & 3, wn = wid >> 2;
    int group = lane >> 2, tg = lane & 3;

    const float* apt[4];
    const float* bpt[4];
    int rowv[4], kcv[4];
    #pragma unroll
    for (int i = 0; i < 4; i++) {
        int f = tid + i * 256;
        int row = f >> 3, kc = (f & 7) * 4;
        rowv[i] = row; kcv[i] = kc;
        int ar = bm + row;
        apt[i] = (ar < TT) ? (A + (size_t)ar * lda + kc) : nullptr;
        int br = bn + row;
        bpt[i] = (br < Nb) ? (B + (size_t)br * ldb + kc) : nullptr;
    }

    float acc[2][8][4];
    #pragma unroll
    for (int mi = 0; mi < 2; mi++)
        #pragma unroll
        for (int ni = 0; ni < 8; ni++)
            #pragma unroll
            for (int q = 0; q < 4; q++) acc[mi][ni][q] = 0.f;

    float4 ra[4], rb[4];
    {
        int k0 = kt_begin * 32;
        #pragma unroll
        for (int i = 0; i < 4; i++) {
            float4 z = make_float4(0.f, 0.f, 0.f, 0.f);
            ra[i] = apt[i] ? *(const float4*)(apt[i] + k0) : z;
            rb[i] = bpt[i] ? *(const float4*)(bpt[i] + k0) : z;
        }
    }

    for (int kt = kt_begin; kt < kt_end; kt++) {
        __syncthreads();
        #pragma unroll
        for (int i = 0; i < 4; i++) {
            int off = rowv[i] * LDP + kcv[i];
            uint4 h, l;
            f2tf32x2(ra[i].x, h.x, l.x); f2tf32x2(ra[i].y, h.y, l.y);
            f2tf32x2(ra[i].z, h.z, l.z); f2tf32x2(ra[i].w, h.w, l.w);
            *(uint4*)(AHI + off) = h;
            *(uint4*)(ALO + off) = l;
            f2tf32x2(rb[i].x, h.x, l.x); f2tf32x2(rb[i].y, h.y, l.y);
            f2tf32x2(rb[i].z, h.z, l.z); f2tf32x2(rb[i].w, h.w, l.w);
            *(uint4*)(BHI + off) = h;
            *(uint4*)(BLO + off) = l;
        }
        __syncthreads();

        if (kt + 1 < kt_end) {
            int k0 = (kt + 1) * 32;
            #pragma unroll
            for (int i = 0; i < 4; i++) {
                float4 z = make_float4(0.f, 0.f, 0.f, 0.f);
                ra[i] = apt[i] ? *(const float4*)(apt[i] + k0) : z;
                rb[i] = bpt[i] ? *(const float4*)(bpt[i] + k0) : z;
            }
        }

        #pragma unroll
        for (int ks = 0; ks < 4; ks++) {
            int kb = ks * 8 + tg;
            uint32_t ah[2][4], al[2][4];
            #pragma unroll
            for (int mi = 0; mi < 2; mi++) {
                int r0 = (wm * 32 + mi * 16 + group) * LDP;
                ah[mi][0] = AHI[r0 + kb];
                ah[mi][1] = AHI[r0 + 8 * LDP + kb];
                ah[mi][2] = AHI[r0 + kb + 4];
                ah[mi][3] = AHI[r0 + 8 * LDP + kb + 4];
                al[mi][0] = ALO[r0 + kb];
                al[mi][1] = ALO[r0 + 8 * LDP + kb];
                al[mi][2] = ALO[r0 + kb + 4];
                al[mi][3] = ALO[r0 + 8 * LDP + kb + 4];
            }
            #pragma unroll
            for (int ni = 0; ni < 8; ni++) {
                int nr = (wn * 64 + ni * 8 + group) * LDP;
                uint32_t bh0 = BHI[nr + kb], bh1 = BHI[nr + kb + 4];
                uint32_t bl0 = BLO[nr + kb], bl1 = BLO[nr + kb + 4];
                #pragma unroll
                for (int mi = 0; mi < 2; mi++) {
                    MMA8(acc[mi][ni], ah[mi][0], ah[mi][1], ah[mi][2], ah[mi][3], bh0, bh1);
                    MMA8(acc[mi][ni], ah[mi][0], ah[mi][1], ah[mi][2], ah[mi][3], bl0, bl1);
                    MMA8(acc[mi][ni], al[mi][0], al[mi][1], al[mi][2], al[mi][3], bh0, bh1);
                }
            }
        }
    }

    #pragma unroll
    for (int mi = 0; mi < 2; mi++) {
        int r0 = bm + wm * 32 + mi * 16 + group;
        #pragma unroll
        for (int ni = 0; ni < 8; ni++) {
            int col = bn + wn * 64 + ni * 8 + 2 * tg;
            if (col >= Ncols) continue;
            if (r0 < TT)
                *(float2*)(C + (size_t)r0 * ldc + col) = make_float2(acc[mi][ni][0], acc[mi][ni][1]);
            if (r0 + 8 < TT)
                *(float2*)(C + (size_t)(r0 + 8) * ldc + col) = make_float2(acc[mi][ni][2], acc[mi][ni][3]);
        }
    }
}

__global__ __launch_bounds__(256, 1) void g_scorer(const float* A, const float* B,
                                                   float* C, size_t cstride) {
    int z = blockIdx.z;
    tf32_gemm_body(A, HH, B, HH, F1, C + (size_t)z * cstride, F1, F1, HH,
                   z * 32, z * 32 + 32);
}

// =================== bf16 3x GEMM (m16n8k16): C = A @ B^T ===================
// Same tiling: CTA 128x128, BK=32 (2 ksteps of K16), 8 warps (4Mx2N), warp 32x64.
#define LDPB 20
#define SMEM_BF (4 * 128 * LDPB * 4)   // 40 KB

template <int EPI>   // 0 none, 1 +bias
__device__ void bf16_gemm_body(const float* __restrict__ A, int lda,
                               const int* __restrict__ aidx,
                               const int* __restrict__ mcnt,
                               const float* __restrict__ B, int ldb, int Nb,
                               const float* __restrict__ bias,
                               float* __restrict__ C, int ldc, int Ncols,
                               int K, int kt_begin, int kt_end) {
    extern __shared__ uint32_t smem_u[];
    uint32_t* AHI = smem_u;
    uint32_t* ALO = smem_u + 128 * LDPB;
    uint32_t* BHI = smem_u + 2 * 128 * LDPB;
    uint32_t* BLO = smem_u + 3 * 128 * LDPB;

    int M = *mcnt;
    int bm = blockIdx.x * 128, bn = blockIdx.y * 128;
    if (bm >= M) return;

    int tid = threadIdx.x, wid = tid >> 5, lane = tid & 31;
    int wm = wid & 3, wn = wid >> 2;
    int group = lane >> 2, tg = lane & 3;

    const float* apt[4];
    const float* bpt[4];
    int rowv[4], kcv[4];
    #pragma unroll
    for (int i = 0; i < 4; i++) {
        int f = tid + i * 256;
        int row = f >> 3, kc = (f & 7) * 4;
        rowv[i] = row; kcv[i] = kc;
        int ar = bm + row;
        apt[i] = (ar < M) ? (A + (size_t)(aidx ? aidx[ar] : ar) * lda + kc) : nullptr;
        int br = bn + row;
        bpt[i] = (br < Nb) ? (B + (size_t)br * ldb + kc) : nullptr;
    }

    float acc[2][8][4];
    #pragma unroll
    for (int mi = 0; mi < 2; mi++)
        #pragma unroll
        for (int ni = 0; ni < 8; ni++)
            #pragma unroll
            for (int q = 0; q < 4; q++) acc[mi][ni][q] = 0.f;

    float4 ra[4], rb[4];
    {
        int k0 = kt_begin * 32;
        #pragma unroll
        for (int i = 0; i < 4; i++) {
            int gk = k0 + kcv[i];
            float4 z = make_float4(0.f, 0.f, 0.f, 0.f);
            ra[i] = (apt[i] && gk < K) ? *(const float4*)(apt[i] + k0) : z;
            rb[i] = (bpt[i] && gk < K) ? *(const float4*)(bpt[i] + k0) : z;
        }
    }

    for (int kt = kt_begin; kt < kt_end; kt++) {
        __syncthreads();
        #pragma unroll
        for (int i = 0; i < 4; i++) {
            int off = rowv[i] * LDPB + (kcv[i] >> 1);   // pair index
            uint2 h, l;
            f2bf2(ra[i].x, ra[i].y, h.x, l.x);
            f2bf2(ra[i].z, ra[i].w, h.y, l.y);
            *(uint2*)(AHI + off) = h;
            *(uint2*)(ALO + off) = l;
            f2bf2(rb[i].x, rb[i].y, h.x, l.x);
            f2bf2(rb[i].z, rb[i].w, h.y, l.y);
            *(uint2*)(BHI + off) = h;
            *(uint2*)(BLO + off) = l;
        }
        __syncthreads();

        if (kt + 1 < kt_end) {
            int k0 = (kt + 1) * 32;
            #pragma unroll
            for (int i = 0; i < 4; i++) {
                int gk = k0 + kcv[i];
                float4 z = make_float4(0.f, 0.f, 0.f, 0.f);
                ra[i] = (apt[i] && gk < K) ? *(const float4*)(apt[i] + k0) : z;
                rb[i] = (bpt[i] && gk < K) ? *(const float4*)(bpt[i] + k0) : z;
            }
        }

        #pragma unroll
        for (int ks = 0; ks < 2; ks++) {
            int kb = ks * 8 + tg;              // bf16-pair index base
            uint32_t ah[2][4], al[2][4];
            #pragma unroll
            for (int mi = 0; mi < 2; mi++) {
                int r0 = (wm * 32 + mi * 16 + group) * LDPB;
                ah[mi][0] = AHI[r0 + kb];
                ah[mi][1] = AHI[r0 + 8 * LDPB + kb];
                ah[mi][2] = AHI[r0 + kb + 4];
                ah[mi][3] = AHI[r0 + 8 * LDPB + kb + 4];
                al[mi][0] = ALO[r0 + kb];
                al[mi][1] = ALO[r0 + 8 * LDPB + kb];
                al[mi][2] = ALO[r0 + kb + 4];
                al[mi][3] = ALO[r0 + 8 * LDPB + kb + 4];
            }
            #pragma unroll
            for (int ni = 0; ni < 8; ni++) {
                int nr = (wn * 64 + ni * 8 + group) * LDPB;
                uint32_t bh0 = BHI[nr + kb], bh1 = BHI[nr + kb + 4];
                uint32_t bl0 = BLO[nr + kb], bl1 = BLO[nr + kb + 4];
                #pragma unroll
                for (int mi = 0; mi < 2; mi++) {
                    MMA16(acc[mi][ni], ah[mi][0], ah[mi][1], ah[mi][2], ah[mi][3], bh0, bh1);
                    MMA16(acc[mi][ni], ah[mi][0], ah[mi][1], ah[mi][2], ah[mi][3], bl0, bl1);
                    MMA16(acc[mi][ni], al[mi][0], al[mi][1], al[mi][2], al[mi][3], bh0, bh1);
                }
            }
        }
    }

    #pragma unroll
    for (int mi = 0; mi < 2; mi++) {
        int r0 = bm + wm * 32 + mi * 16 + group;
        #pragma unroll
        for (int ni = 0; ni < 8; ni++) {
            int col = bn + wn * 64 + ni * 8 + 2 * tg;
            if (col >= Ncols) continue;
            float b0 = 0.f, b1 = 0.f;
            if (EPI == 1) { b0 = bias[col]; b1 = bias[col + 1]; }
            if (r0 < M)
                *(float2*)(C + (size_t)r0 * ldc + col) =
                    make_float2(acc[mi][ni][0] + b0, acc[mi][ni][1] + b1);
            if (r0 + 8 < M)
                *(float2*)(C + (size_t)(r0 + 8) * ldc + col) =
                    make_float2(acc[mi][ni][2] + b0, acc[mi][ni][3] + b1);
        }
    }
}

__global__ __launch_bounds__(256, 1) void g_layer(const float* x, const float* w,
                                                  const float* b, float* C) {
    bf16_gemm_body<1>(x, HH, g_cidx, &g_cnt[0], w, HH, HH, b, C, HH, HH, HH, 0, 64);
}

__global__ __launch_bounds__(256, 1) void g_tsel(const float* x,
                                                 const float* u4, const float* u12,
                                                 const float* u40, const float* u128) {
    int ri = g_flags[2], rv = g_flags[3];
    const float* U = (ri == 0) ? u4 : (ri == 1) ? u12 : (ri == 2) ? u40 : u128;
    int z = blockIdx.z;
    bf16_gemm_body<0>(x, HH, g_nidx, &g_cnt[1], U, HH, rv, nullptr,
                      g_TselP + (size_t)z * TT * 128, 128, 128, HH, z * 8, z * 8 + 8);
}

__global__ void tsel_reduce() {
    int n = g_cnt[1] * 128;
    int i = blockIdx.x * 256 + threadIdx.x;
    if (i >= n) return;
    float s = 0.f;
    #pragma unroll
    for (int z = 0; z < 8; z++) s += g_TselP[(size_t)z * TT * 128 + i];
    g_Tsel[i] = s;
}

__global__ __launch_bounds__(256, 1) void g_lsel(const float* v4, const float* v12,
                                                 const float* v40, const float* v128) {
    int ri = g_flags[2], rv = g_flags[3];
    const float* V = (ri == 0) ? v4 : (ri == 1) ? v12 : (ri == 2) ? v40 : v128;
    bf16_gemm_body<0>(g_Tsel, 128, nullptr, &g_cnt[1], V, rv, HH, nullptr,
                      g_Lsel, HH, HH, rv, 0, (rv + 31) / 32);
}

// =================== small kernels ===================
__global__ void pool_part(const float* __restrict__ x) {
    int i = blockIdx.x * 256 + threadIdx.x;
    int b = i / HH, h = i % HH;
    int c = blockIdx.y;
    const float* p = x + ((size_t)b * SS + (size_t)c * 128) * HH + h;
    float s0 = 0.f, s1 = 0.f, s2 = 0.f, s3 = 0.f;
    #pragma unroll 8
    for (int s = 0; s < 128; s += 4) {
        s0 += p[(size_t)s * HH];
        s1 += p[(size_t)(s + 1) * HH];
        s2 += p[(size_t)(s + 2) * HH];
        s3 += p[(size_t)(s + 3) * HH];
    }
    g_pp[c * BB * HH + i] = s0 + s1 + s2 + s3;
}

__global__ void pool_reduce() {
    int i = blockIdx.x * 256 + threadIdx.x;
    float s = 0.f;
    #pragma unroll
    for (int c = 0; c < 8; c++) s += g_pp[c * BB * HH + i];
    g_pooled[i] = s * (1.0f / SS);
}

__global__ void dots_kernel(const float* __restrict__ key_proj_w,
                            const float* __restrict__ ce_w1,
                            const float* __restrict__ ce_b1) {
    int j = blockIdx.x;
    int tid = threadIdx.x;
    const float* pooled;
    const float* w;
    if (j < 64) {
        int b = j / KD, d = j % KD;
        pooled = g_pooled + (size_t)b * HH;
        w = key_proj_w + (size_t)d * HH;
    } else {
        int jj = j - 64;
        int b = jj / CEH, f = jj % CEH;
        pooled = g_pooled + (size_t)b * HH;
        w = ce_w1 + (size_t)f * HH;
    }
    float part = 0.f;
    for (int k = tid; k < HH; k += 256) part += pooled[k] * w[k];
    __shared__ float red[256];
    red[tid] = part;
    __syncthreads();
    for (int st = 128; st > 0; st >>= 1) {
        if (tid < st) red[tid] += red[tid + st];
        __syncthreads();
    }
    if (tid == 0) {
        float v = red[0];
        if (j < 64) {
            g_qk[j] = v;
        } else {
            int jj = j - 64;
            int f = jj % CEH;
            v += ce_b1[f];
            g_ceh[jj] = fmaxf(v, 0.f);
        }
    }
}

// parallel cache lookup + rank selection (1 block, 256 threads)
__global__ void select_kernel(const float* __restrict__ cache_keys,
                              const float* __restrict__ ce_w2,
                              const float* __restrict__ ce_b2) {
    __shared__ float qfn[64];
    __shared__ float sims[16];
    __shared__ float scores[8];
    __shared__ float s_qnorm;
    int tid = threadIdx.x, warp = tid >> 5, lane = tid & 31;

    // per-batch normalization of qk (warps 0,1)
    if (warp < 2) {
        float v = g_qk[warp * 32 + lane];
        float s = v * v;
        #pragma unroll
        for (int o = 16; o > 0; o >>= 1) s += __shfl_xor_sync(0xffffffffu, s, o);
        float inv = 1.0f / fmaxf(sqrtf(s), 1e-8f);
        qfn[warp * 32 + lane] = v * inv;
    }
    // scores: warp w -> (b,r) entry w (needs only g_ceh)
    {
        int b = warp >> 2, r = warp & 3;
        float s = (lane < 32) ? g_ceh[b * CEH + lane] * ce_w2[r * CEH + lane] : 0.f;
        s += g_ceh[b * CEH + 32 + lane] * ce_w2[r * CEH + 32 + lane];
        #pragma unroll
        for (int o = 16; o > 0; o >>= 1) s += __shfl_xor_sync(0xffffffffu, s, o);
        if (lane == 0) scores[warp] = s + ce_b2[r];
    }
    __syncthreads();
    if (tid < 32) {
        float s = qfn[tid] * qfn[tid] + qfn[32 + tid] * qfn[32 + tid];
        #pragma unroll
        for (int o = 16; o > 0; o >>= 1) s += __shfl_xor_sync(0xffffffffu, s, o);
        if (tid == 0) s_qnorm = sqrtf(s);
    }
    __syncthreads();
    // sims: entry = tid>>4, 16 lanes per entry, 4 elems each
    {
        int e = tid >> 4, sub = tid & 15;
        float d = 0.f, n = 0.f;
        #pragma unroll
        for (int i = 0; i < 4; i++) {
            float c = cache_keys[e * 64 + sub * 4 + i];
            d += c * qfn[sub * 4 + i];
            n += c * c;
        }
        #pragma unroll
        for (int o = 8; o > 0; o >>= 1) {
            d += __shfl_xor_sync(0xffffffffu, d, o);
            n += __shfl_xor_sync(0xffffffffu, n, o);
        }
        if (sub == 0)
            sims[e] = d / (fmaxf(sqrtf(n), 1e-8f) * fmaxf(s_qnorm, 1e-8f));
    }
    __syncthreads();
    if (tid == 0) {
        int best = 0;
        float bv = sims[0];
        for (int n = 1; n < NCACHE; n++)
            if (sims[n] > bv) { bv = sims[n]; best = n; }
        g_flags[0] = best;
        g_flags[1] = (bv >= 0.95f) ? 1 : 0;
        int bi = 0;
        float sv = scores[0];
        for (int i = 1; i < 8; i++)
            if (scores[i] > sv) { sv = scores[i]; bi = i; }
        int ri = bi % 4;
        g_flags[2] = ri;
        g_flags[3] = (ri == 0) ? 4 : (ri == 1) ? 12 : (ri == 2) ? 40 : 128;
    }
}

__global__ void imp_kernel(const float* __restrict__ w2,
                           const float* __restrict__ b2,
                           const float* __restrict__ b1,
                           const float* __restrict__ pos) {
    int warp = threadIdx.x >> 5, lane = threadIdx.x & 31;
    int t = blockIdx.x * 8 + warp;
    float s = 0.f;
    const float* p0 = g_hP + (size_t)t * F1;
    const float* p1 = g_hP + (size_t)TT * F1 + (size_t)t * F1;
    for (int f = lane; f < F1; f += 32) {
        float h = fmaxf(p0[f] + p1[f] + b1[f], 0.f);
        s += h * w2[f];
    }
    #pragma unroll
    for (int o = 16; o > 0; o >>= 1) s += __shfl_xor_sync(0xffffffffu, s, o);
    if (lane == 0) {
        int spos = t % SS;
        float z = s + b2[0] + 0.1f * pos[spos];
        float imp = 1.0f / (1.0f + expf(-z));
        if (spos == 0 || spos == SS - 1) imp *= 2.0f;
        g_crit[t] = (imp > 0.8f) ? 1 : 0;
        g_simp[t] = (imp < 0.3f) ? 1 : 0;
    }
}

__global__ void compact_kernel() {
    int lane = threadIdx.x;
    int cb = 0, nb = 0;
    for (int it = 0; it < TT / 32; it++) {
        int t = it * 32 + lane;
        int c = g_crit[t], s = g_simp[t];
        int nn = !(c || s);
        unsigned cm = __ballot_sync(0xffffffffu, c);
        unsigned nm = __ballot_sync(0xffffffffu, nn);
        unsigned lt = (1u << lane) - 1u;
        if (c) { int p = cb + __popc(cm & lt); g_cidx[p] = t; g_pos[t] = p; }
        if (nn) { int p = nb + __popc(nm & lt); g_nidx[p] = t; g_pos[t] = p; }
        cb += __popc(cm);
        nb += __popc(nm);
    }
    if (lane == 0) { g_cnt[0] = cb; g_cnt[1] = nb; }
}

__global__ void t4_kernel(const float* __restrict__ x, const float* __restrict__ u4) {
    int warp = threadIdx.x >> 5, lane = threadIdx.x & 31;
    int t = blockIdx.x * 8 + warp;
    float a0 = 0.f, a1 = 0.f, a2 = 0.f, a3 = 0.f;
    const float* xr = x + (size_t)t * HH;
    for (int k = lane; k < HH; k += 32) {
        float xv = xr[k];
        a0 += xv * u4[k];
        a1 += xv * u4[HH + k];
        a2 += xv * u4[2 * HH + k];
        a3 += xv * u4[3 * HH + k];
    }
    #pragma unroll
    for (int o = 16; o > 0; o >>= 1) {
        a0 += __shfl_xor_sync(0xffffffffu, a0, o);
        a1 += __shfl_xor_sync(0xffffffffu, a1, o);
        a2 += __shfl_xor_sync(0xffffffffu, a2, o);
        a3 += __shfl_xor_sync(0xffffffffu, a3, o);
    }
    if (lane == 0) {
        g_T4[t * 4 + 0] = a0;
        g_T4[t * 4 + 1] = a1;
        g_T4[t * 4 + 2] = a2;
        g_T4[t * 4 + 3] = a3;
    }
}

__device__ __forceinline__ float4 f4add(float4 a, float4 b) {
    return make_float4(a.x + b.x, a.y + b.y, a.z + b.z, a.w + b.w);
}

__global__ __launch_bounds__(256) void final_kernel(const float* __restrict__ x,
                                                    const float* __restrict__ deltas,
                                                    const float* __restrict__ v4,
                                                    float* __restrict__ out) {
    int t = blockIdx.x;
    int tid = threadIdx.x;
    int crit = g_crit[t], simp = g_simp[t];
    const float4* x4 = (const float4*)(x + (size_t)t * HH);
    float4* o4 = (float4*)(out + (size_t)t * HH);

    if (crit) {
        const float4* y4 = (const float4*)(g_Y + (size_t)g_pos[t] * HH);
        #pragma unroll
        for (int r = 0; r < 2; r++) {
            int i = r * 256 + tid;
            o4[i] = y4[i];
        }
    } else if (simp) {
        if (g_flags[1]) {
            const float4* d4 = (const float4*)(deltas + (size_t)g_flags[0] * TT * HH + (size_t)t * HH);
            #pragma unroll
            for (int r = 0; r < 2; r++) {
                int i = r * 256 + tid;
                o4[i] = f4add(x4[i], d4[i]);
            }
        } else {
            float t0 = g_T4[t * 4 + 0], t1 = g_T4[t * 4 + 1];
            float t2 = g_T4[t * 4 + 2], t3 = g_T4[t * 4 + 3];
            const float4* v44 = (const float4*)v4;
            #pragma unroll
            for (int r = 0; r < 2; r++) {
                int i = r * 256 + tid;
                int h = i * 4;
                float4 xv = x4[i];
                float lr[4];
                #pragma unroll
                for (int j = 0; j < 4; j++) {
                    float4 vr = v44[h + j];
                    lr[j] = t0 * vr.x + t1 * vr.y + t2 * vr.z + t3 * vr.w;
                }
                o4[i] = make_float4(xv.x + lr[0], xv.y + lr[1], xv.z + lr[2], xv.w + lr[3]);
            }
        }
    } else {
        const float4* l4 = (const float4*)(g_Lsel + (size_t)g_pos[t] * HH);
        #pragma unroll
        for (int r = 0; r < 2; r++) {
            int i = r * 256 + tid;
            o4[i] = f4add(x4[i], l4[i]);
        }
    }
}

// =================== launch ===================
extern "C" void kernel_launch(void* const* d_in, const int* in_sizes, int n_in,
                              void* d_out, int out_size) {
    const float* x          = (const float*)d_in[0];
    const float* scorer_w1  = (const float*)d_in[1];
    const float* scorer_b1  = (const float*)d_in[2];
    const float* scorer_w2  = (const float*)d_in[3];
    const float* scorer_b2  = (const float*)d_in[4];
    const float* pos_imp    = (const float*)d_in[5];
    const float* key_proj_w = (const float*)d_in[6];
    const float* cache_keys = (const float*)d_in[7];
    const float* cache_del  = (const float*)d_in[8];
    const float* ce_w1      = (const float*)d_in[9];
    const float* ce_b1      = (const float*)d_in[10];
    const float* ce_w2      = (const float*)d_in[11];
    const float* ce_b2      = (const float*)d_in[12];
    const float* u4   = (const float*)d_in[13];
    const float* v4   = (const float*)d_in[14];
    const float* u12  = (const float*)d_in[15];
    const float* v12  = (const float*)d_in[16];
    const float* u40  = (const float*)d_in[17];
    const float* v40  = (const float*)d_in[18];
    const float* u128 = (const float*)d_in[19];
    const float* v128 = (const float*)d_in[20];
    const float* layer_w = (const float*)d_in[21];
    const float* layer_b = (const float*)d_in[22];
    float* out = (float*)d_out;

    float* d_hP; cudaGetSymbolAddress((void**)&d_hP, g_hP);
    float* d_Y;  cudaGetSymbolAddress((void**)&d_Y, g_Y);

    cudaFuncSetAttribute(g_scorer, cudaFuncAttributeMaxDynamicSharedMemorySize, SMEM_TF);

    // 1) pooled mean over S
    pool_part<<<dim3(16, 8), 256>>>(x);
    pool_reduce<<<16, 256>>>();
    // 2) pooled dots + selection flags
    dots_kernel<<<192, 256>>>(key_proj_w, ce_w1, ce_b1);
    select_kernel<<<1, 256>>>(cache_keys, ce_w2, ce_b2);
    // 3) scorer GEMM (tf32 3x, mask-critical), split-K x2
    g_scorer<<<dim3(16, 4, 2), 256, SMEM_TF>>>(x, scorer_w1, d_hP, (size_t)TT * F1);
    // 4) importance + masks (fused bias+relu+dot)
    imp_kernel<<<256, 256>>>(scorer_w2, scorer_b2, scorer_b1, pos_imp);
    // 5) compaction
    compact_kernel<<<1, 32>>>();
    // 6) layer GEMM on critical tokens (bf16 3x)
    g_layer<<<dim3(16, 16), 256, SMEM_BF>>>(x, layer_w, layer_b, d_Y);
    // 7) T4 (simple-miss path)
    t4_kernel<<<256, 256>>>(x, u4);
    // 8) Tsel on normal tokens (bf16 3x), split-K x8, then reduce
    g_tsel<<<dim3(16, 1, 8), 256, SMEM_BF>>>(x, u4, u12, u40, u128);
    tsel_reduce<<<TT * 128 / 256, 256>>>();
    // 9) Lsel on normal tokens (bf16 3x)
    g_lsel<<<dim3(16, 16), 256, SMEM_BF>>>(v4, v12, v40, v128);
    // 10) route per token
    final_kernel<<<TT, 256>>>(x, cache_del, v4, out);
}

// round 6
// speedup vs baseline: 4.1282x; 1.1144x over previous
#include <cuda_runtime.h>
#include <cuda_bf16.h>
#include <cstdint>
#include <math.h>

// Problem constants
#define BB 2
#define SS 1024
#define HH 2048
#define TT (BB*SS)      // 2048 tokens
#define F1 512          // H/4
#define KD 32
#define NCACHE 16
#define CEH 64
#define NSPLIT_T 32     // tsel split-K factor

// ---------------- scratch (static device memory; no allocations) ----------------
__device__ float g_hP[2 * TT * F1];          // scorer split-K partials
__device__ float g_Y[TT * HH];               // layer output (compact critical rows)
__device__ float g_Lsel[TT * HH];            // low-rank update (compact normal rows)
__device__ float g_Tsel[TT * 128];           // compact normal rows @ Usel^T
__device__ float g_TselP[NSPLIT_T * TT * 128];
__device__ float g_T4[TT * 4];
__device__ float g_pp[8 * BB * HH];
__device__ unsigned char g_crit[TT];
__device__ unsigned char g_simp[TT];
__device__ int g_cidx[TT];
__device__ int g_nidx[TT];
__device__ int g_pos[TT];
__device__ int g_cnt[2];
__device__ int g_flags[4];
__device__ int g_nflag;                      // near-threshold token count
__device__ int g_flist[64];                  // near-threshold token list

// z-space mask thresholds (sigmoid-equivalent)
#define ZC_NORM  1.3862944f    // sigmoid(z)>0.8
#define ZS_NORM (-0.8472979f)  // sigmoid(z)<0.3
#define ZC_EDGE (-0.4054651f)  // 2*sigmoid(z)>0.8
#define ZS_EDGE (-1.7346011f)  // 2*sigmoid(z)<0.3
#define Z_GUARD  2e-3f

// =================== conversion helpers ===================
__device__ __forceinline__ void f2bf2(float x, float y, uint32_t& hi, uint32_t& lo) {
    __nv_bfloat162 h = __floats2bfloat162_rn(x, y);
    float rx = x - __bfloat162float(h.x);
    float ry = y - __bfloat162float(h.y);
    __nv_bfloat162 l = __floats2bfloat162_rn(rx, ry);
    hi = *(uint32_t*)&h;
    lo = *(uint32_t*)&l;
}

#define MMA16(c, a0, a1, a2, a3, b0, b1) \
    asm volatile("mma.sync.aligned.m16n8k16.row.col.f32.bf16.bf16.f32 " \
                 "{%0,%1,%2,%3},{%4,%5,%6,%7},{%8,%9},{%0,%1,%2,%3};" \
                 : "+f"((c)[0]), "+f"((c)[1]), "+f"((c)[2]), "+f"((c)[3]) \
                 : "r"(a0), "r"(a1), "r"(a2), "r"(a3), "r"(b0), "r"(b1))

// =================== bf16 3x GEMM (m16n8k16): C = A @ B^T ===================
// CTA tile 128x128, BK=32 (2 ksteps), 8 warps (4Mx2N), warp 32x64.
#define LDPB 20
#define SMEM_BF (4 * 128 * LDPB * 4)   // 40 KB

template <int EPI>   // 0 none, 1 +bias
__device__ void bf16_gemm_body(const float* __restrict__ A, int lda,
                               const int* __restrict__ aidx,
                               const int* __restrict__ mcnt, int Mstat,
                               const float* __restrict__ B, int ldb, int Nb,
                               const float* __restrict__ bias,
                               float* __restrict__ C, int ldc, int Ncols,
                               int K, int kt_begin, int kt_end) {
    extern __shared__ uint32_t smem_u[];
    uint32_t* AHI = smem_u;
    uint32_t* ALO = smem_u + 128 * LDPB;
    uint32_t* BHI = smem_u + 2 * 128 * LDPB;
    uint32_t* BLO = smem_u + 3 * 128 * LDPB;

    int M = mcnt ? *mcnt : Mstat;
    int bm = blockIdx.x * 128, bn = blockIdx.y * 128;
    if (bm >= M) return;

    int tid = threadIdx.x, wid = tid >> 5, lane = tid & 31;
    int wm = wid & 3, wn = wid >> 2;
    int group = lane >> 2, tg = lane & 3;

    const float* apt[4];
    const float* bpt[4];
    int rowv[4], kcv[4];
    #pragma unroll
    for (int i = 0; i < 4; i++) {
        int f = tid + i * 256;
        int row = f >> 3, kc = (f & 7) * 4;
        rowv[i] = row; kcv[i] = kc;
        int ar = bm + row;
        apt[i] = (ar < M) ? (A + (size_t)(aidx ? aidx[ar] : ar) * lda + kc) : nullptr;
        int br = bn + row;
        bpt[i] = (br < Nb) ? (B + (size_t)br * ldb + kc) : nullptr;
    }

    float acc[2][8][4];
    #pragma unroll
    for (int mi = 0; mi < 2; mi++)
        #pragma unroll
        for (int ni = 0; ni < 8; ni++)
            #pragma unroll
            for (int q = 0; q < 4; q++) acc[mi][ni][q] = 0.f;

    float4 ra[4], rb[4];
    {
        int k0 = kt_begin * 32;
        #pragma unroll
        for (int i = 0; i < 4; i++) {
            int gk = k0 + kcv[i];
            float4 z = make_float4(0.f, 0.f, 0.f, 0.f);
            ra[i] = (apt[i] && gk < K) ? *(const float4*)(apt[i] + k0) : z;
            rb[i] = (bpt[i] && gk < K) ? *(const float4*)(bpt[i] + k0) : z;
        }
    }

    for (int kt = kt_begin; kt < kt_end; kt++) {
        __syncthreads();
        #pragma unroll
        for (int i = 0; i < 4; i++) {
            int off = rowv[i] * LDPB + (kcv[i] >> 1);
            uint2 h, l;
            f2bf2(ra[i].x, ra[i].y, h.x, l.x);
            f2bf2(ra[i].z, ra[i].w, h.y, l.y);
            *(uint2*)(AHI + off) = h;
            *(uint2*)(ALO + off) = l;
            f2bf2(rb[i].x, rb[i].y, h.x, l.x);
            f2bf2(rb[i].z, rb[i].w, h.y, l.y);
            *(uint2*)(BHI + off) = h;
            *(uint2*)(BLO + off) = l;
        }
        __syncthreads();

        if (kt + 1 < kt_end) {
            int k0 = (kt + 1) * 32;
            #pragma unroll
            for (int i = 0; i < 4; i++) {
                int gk = k0 + kcv[i];
                float4 z = make_float4(0.f, 0.f, 0.f, 0.f);
                ra[i] = (apt[i] && gk < K) ? *(const float4*)(apt[i] + k0) : z;
                rb[i] = (bpt[i] && gk < K) ? *(const float4*)(bpt[i] + k0) : z;
            }
        }

        #pragma unroll
        for (int ks = 0; ks < 2; ks++) {
            int kb = ks * 8 + tg;
            uint32_t ah[2][4], al[2][4];
            #pragma unroll
            for (int mi = 0; mi < 2; mi++) {
                int r0 = (wm * 32 + mi * 16 + group) * LDPB;
                ah[mi][0] = AHI[r0 + kb];
                ah[mi][1] = AHI[r0 + 8 * LDPB + kb];
                ah[mi][2] = AHI[r0 + kb + 4];
                ah[mi][3] = AHI[r0 + 8 * LDPB + kb + 4];
                al[mi][0] = ALO[r0 + kb];
                al[mi][1] = ALO[r0 + 8 * LDPB + kb];
                al[mi][2] = ALO[r0 + kb + 4];
                al[mi][3] = ALO[r0 + 8 * LDPB + kb + 4];
            }
            #pragma unroll
            for (int ni = 0; ni < 8; ni++) {
                int nr = (wn * 64 + ni * 8 + group) * LDPB;
                uint32_t bh0 = BHI[nr + kb], bh1 = BHI[nr + kb + 4];
                uint32_t bl0 = BLO[nr + kb], bl1 = BLO[nr + kb + 4];
                #pragma unroll
                for (int mi = 0; mi < 2; mi++) {
                    MMA16(acc[mi][ni], ah[mi][0], ah[mi][1], ah[mi][2], ah[mi][3], bh0, bh1);
                    MMA16(acc[mi][ni], ah[mi][0], ah[mi][1], ah[mi][2], ah[mi][3], bl0, bl1);
                    MMA16(acc[mi][ni], al[mi][0], al[mi][1], al[mi][2], al[mi][3], bh0, bh1);
                }
            }
        }
    }

    #pragma unroll
    for (int mi = 0; mi < 2; mi++) {
        int r0 = bm + wm * 32 + mi * 16 + group;
        #pragma unroll
        for (int ni = 0; ni < 8; ni++) {
            int col = bn + wn * 64 + ni * 8 + 2 * tg;
            if (col >= Ncols) continue;
            float b0 = 0.f, b1 = 0.f;
            if (EPI == 1) { b0 = bias[col]; b1 = bias[col + 1]; }
            if (r0 < M)
                *(float2*)(C + (size_t)r0 * ldc + col) =
                    make_float2(acc[mi][ni][0] + b0, acc[mi][ni][1] + b1);
            if (r0 + 8 < M)
                *(float2*)(C + (size_t)(r0 + 8) * ldc + col) =
                    make_float2(acc[mi][ni][2] + b0, acc[mi][ni][3] + b1);
        }
    }
}

__global__ __launch_bounds__(256, 1) void g_scorer(const float* x, const float* w1,
                                                   float* C) {
    int z = blockIdx.z;
    bf16_gemm_body<0>(x, HH, nullptr, nullptr, TT, w1, HH, F1, nullptr,
                      C + (size_t)z * TT * F1, F1, F1, HH, z * 32, z * 32 + 32);
}

__global__ __launch_bounds__(256, 1) void g_layer(const float* x, const float* w,
                                                  const float* b, float* C) {
    bf16_gemm_body<1>(x, HH, g_cidx, &g_cnt[0], 0, w, HH, HH, b, C, HH, HH, HH, 0, 64);
}

__global__ __launch_bounds__(256, 1) void g_tsel(const float* x,
                                                 const float* u4, const float* u12,
                                                 const float* u40, const float* u128) {
    int ri = g_flags[2], rv = g_flags[3];
    const float* U = (ri == 0) ? u4 : (ri == 1) ? u12 : (ri == 2) ? u40 : u128;
    int z = blockIdx.z;
    bf16_gemm_body<0>(x, HH, g_nidx, &g_cnt[1], 0, U, HH, rv, nullptr,
                      g_TselP + (size_t)z * TT * 128, 128, 128, HH, z * 2, z * 2 + 2);
}

__global__ void tsel_reduce() {
    int n = g_cnt[1] * 128;
    int i = blockIdx.x * 256 + threadIdx.x;
    if (i >= n) return;
    float s = 0.f;
    #pragma unroll
    for (int z = 0; z < NSPLIT_T; z++) s += g_TselP[(size_t)z * TT * 128 + i];
    g_Tsel[i] = s;
}

__global__ __launch_bounds__(256, 1) void g_lsel(const float* v4, const float* v12,
                                                 const float* v40, const float* v128) {
    int ri = g_flags[2], rv = g_flags[3];
    const float* V = (ri == 0) ? v4 : (ri == 1) ? v12 : (ri == 2) ? v40 : v128;
    bf16_gemm_body<0>(g_Tsel, 128, nullptr, &g_cnt[1], 0, V, rv, HH, nullptr,
                      g_Lsel, HH, HH, rv, 0, (rv + 31) / 32);
}

// =================== small kernels ===================
__global__ void pool_part(const float* __restrict__ x) {
    int i = blockIdx.x * 256 + threadIdx.x;
    int b = i / HH, h = i % HH;
    int c = blockIdx.y;
    const float* p = x + ((size_t)b * SS + (size_t)c * 128) * HH + h;
    float s0 = 0.f, s1 = 0.f, s2 = 0.f, s3 = 0.f;
    #pragma unroll 8
    for (int s = 0; s < 128; s += 4) {
        s0 += p[(size_t)s * HH];
        s1 += p[(size_t)(s + 1) * HH];
        s2 += p[(size_t)(s + 2) * HH];
        s3 += p[(size_t)(s + 3) * HH];
    }
    g_pp[c * BB * HH + i] = s0 + s1 + s2 + s3;
}

// fused: pool_reduce + dots + cache/rank selection + recheck-counter reset
__global__ __launch_bounds__(1024) void prep_kernel(const float* __restrict__ key_proj_w,
                                                    const float* __restrict__ ce_w1,
                                                    const float* __restrict__ ce_b1,
                                                    const float* __restrict__ cache_keys,
                                                    const float* __restrict__ ce_w2,
                                                    const float* __restrict__ ce_b2) {
    __shared__ float pooled[BB * HH];     // 16 KB
    __shared__ float qk_s[64];
    __shared__ float qfn[64];
    __shared__ float ceh[2 * CEH];
    __shared__ float sims[16];
    __shared__ float scores[8];
    __shared__ float s_qnorm;
    int tid = threadIdx.x, warp = tid >> 5, lane = tid & 31;

    if (tid == 0) g_nflag = 0;

    // pool reduce
    for (int i = tid; i < BB * HH; i += 1024) {
        float s = 0.f;
        #pragma unroll
        for (int c = 0; c < 8; c++) s += g_pp[c * BB * HH + i];
        pooled[i] = s * (1.0f / SS);
    }
    __syncthreads();

    // 192 dots of K=2048: warp w handles j = w + 32*c
    for (int c = 0; c < 6; c++) {
        int j = warp + 32 * c;
        const float* pl;
        const float* w;
        if (j < 64) {
            pl = pooled + (j / KD) * HH;
            w = key_proj_w + (size_t)(j % KD) * HH;
        } else {
            int jj = j - 64;
            pl = pooled + (jj / CEH) * HH;
            w = ce_w1 + (size_t)(jj % CEH) * HH;
        }
        float s = 0.f;
        for (int k = lane; k < HH; k += 32) s += pl[k] * w[k];
        #pragma unroll
        for (int o = 16; o > 0; o >>= 1) s += __shfl_xor_sync(0xffffffffu, s, o);
        if (lane == 0) {
            if (j < 64) qk_s[j] = s;
            else {
                int jj = j - 64;
                ceh[jj] = fmaxf(s + ce_b1[jj % CEH], 0.f);
            }
        }
    }
    __syncthreads();

    // normalize qk per batch (warps 0,1); scores (warps 0..7)
    if (warp < 2) {
        float v = qk_s[warp * 32 + lane];
        float s = v * v;
        #pragma unroll
        for (int o = 16; o > 0; o >>= 1) s += __shfl_xor_sync(0xffffffffu, s, o);
        qfn[warp * 32 + lane] = v * (1.0f / fmaxf(sqrtf(s), 1e-8f));
    }
    if (warp >= 8 && warp < 16) {
        int w8 = warp - 8;
        int b = w8 >> 2, r = w8 & 3;
        float s = ceh[b * CEH + lane] * ce_w2[r * CEH + lane]
                + ceh[b * CEH + 32 + lane] * ce_w2[r * CEH + 32 + lane];
        #pragma unroll
        for (int o = 16; o > 0; o >>= 1) s += __shfl_xor_sync(0xffffffffu, s, o);
        if (lane == 0) scores[w8] = s + ce_b2[r];
    }
    __syncthreads();
    if (tid < 32) {
        float s = qfn[tid] * qfn[tid] + qfn[32 + tid] * qfn[32 + tid];
        #pragma unroll
        for (int o = 16; o > 0; o >>= 1) s += __shfl_xor_sync(0xffffffffu, s, o);
        if (tid == 0) s_qnorm = sqrtf(s);
    }
    __syncthreads();
    if (tid < 256) {
        int e = tid >> 4, sub = tid & 15;
        float d = 0.f, n = 0.f;
        #pragma unroll
        for (int i = 0; i < 4; i++) {
            float c = cache_keys[e * 64 + sub * 4 + i];
            d += c * qfn[sub * 4 + i];
            n += c * c;
        }
        #pragma unroll
        for (int o = 8; o > 0; o >>= 1) {
            d += __shfl_xor_sync(0xffffffffu, d, o);
            n += __shfl_xor_sync(0xffffffffu, n, o);
        }
        if (sub == 0)
            sims[e] = d / (fmaxf(sqrtf(n), 1e-8f) * fmaxf(s_qnorm, 1e-8f));
    }
    __syncthreads();
    if (tid == 0) {
        int best = 0;
        float bv = sims[0];
        for (int n = 1; n < NCACHE; n++)
            if (sims[n] > bv) { bv = sims[n]; best = n; }
        g_flags[0] = best;
        g_flags[1] = (bv >= 0.95f) ? 1 : 0;
        int bi = 0;
        float sv = scores[0];
        for (int i = 1; i < 8; i++)
            if (scores[i] > sv) { sv = scores[i]; bi = i; }
        int ri = bi % 4;
        g_flags[2] = ri;
        g_flags[3] = (ri == 0) ? 4 : (ri == 1) ? 12 : (ri == 2) ? 40 : 128;
    }
}

// importance: fused bias+relu+dot over scorer partials; flags near-threshold tokens
__global__ void imp_kernel(const float* __restrict__ w2,
                           const float* __restrict__ b2,
                           const float* __restrict__ b1,
                           const float* __restrict__ pos) {
    int warp = threadIdx.x >> 5, lane = threadIdx.x & 31;
    int t = blockIdx.x * 8 + warp;
    float s = 0.f;
    const float* p0 = g_hP + (size_t)t * F1;
    const float* p1 = g_hP + (size_t)TT * F1 + (size_t)t * F1;
    for (int f = lane; f < F1; f += 32) {
        float h = fmaxf(p0[f] + p1[f] + b1[f], 0.f);
        s += h * w2[f];
    }
    #pragma unroll
    for (int o = 16; o > 0; o >>= 1) s += __shfl_xor_sync(0xffffffffu, s, o);
    if (lane == 0) {
        int spos = t % SS;
        float z = s + b2[0] + 0.1f * pos[spos];
        bool edge = (spos == 0 || spos == SS - 1);
        float zc = edge ? ZC_EDGE : ZC_NORM;
        float zs = edge ? ZS_EDGE : ZS_NORM;
        g_crit[t] = (z > zc) ? 1 : 0;
        g_simp[t] = (z < zs) ? 1 : 0;
        if (fabsf(z - zc) < Z_GUARD || fabsf(z - zs) < Z_GUARD) {
            int i = atomicAdd(&g_nflag, 1);
            if (i < 64) g_flist[i] = t;
        }
    }
}

// fp32 recheck of near-threshold tokens (block per flagged token)
__global__ __launch_bounds__(256) void recheck_kernel(const float* __restrict__ x,
                                                      const float* __restrict__ w1,
                                                      const float* __restrict__ b1,
                                                      const float* __restrict__ w2,
                                                      const float* __restrict__ b2,
                                                      const float* __restrict__ pos) {
    int nf = g_nflag; if (nf > 64) nf = 64;
    if ((int)blockIdx.x >= nf) return;
    int t = g_flist[blockIdx.x];

    __shared__ float xs[HH];
    __shared__ float ws[8];
    int tid = threadIdx.x, warp = tid >> 5, lane = tid & 31;
    for (int k = tid; k < HH; k += 256) xs[k] = x[(size_t)t * HH + k];
    __syncthreads();

    float s = 0.f;
    for (int i = 0; i < F1 / 8; i++) {
        int j = warp + i * 8;
        const float* wr = w1 + (size_t)j * HH;
        float d = 0.f;
        for (int k = lane; k < HH; k += 32) d += xs[k] * wr[k];
        #pragma unroll
        for (int o = 16; o > 0; o >>= 1) d += __shfl_xor_sync(0xffffffffu, d, o);
        s += fmaxf(d + b1[j], 0.f) * w2[j];
    }
    if (lane == 0) ws[warp] = s;
    __syncthreads();
    if (tid == 0) {
        float z = b2[0];
        #pragma unroll
        for (int w = 0; w < 8; w++) z += ws[w];
        int spos = t % SS;
        z += 0.1f * pos[spos];
        bool edge = (spos == 0 || spos == SS - 1);
        float zc = edge ? ZC_EDGE : ZC_NORM;
        float zs = edge ? ZS_EDGE : ZS_NORM;
        g_crit[t] = (z > zc) ? 1 : 0;
        g_simp[t] = (z < zs) ? 1 : 0;
    }
}

__global__ void compact_kernel() {
    int lane = threadIdx.x;
    int cb = 0, nb = 0;
    for (int it = 0; it < TT / 32; it++) {
        int t = it * 32 + lane;
        int c = g_crit[t], s = g_simp[t];
        int nn = !(c || s);
        unsigned cm = __ballot_sync(0xffffffffu, c);
        unsigned nm = __ballot_sync(0xffffffffu, nn);
        unsigned lt = (1u << lane) - 1u;
        if (c) { int p = cb + __popc(cm & lt); g_cidx[p] = t; g_pos[t] = p; }
        if (nn) { int p = nb + __popc(nm & lt); g_nidx[p] = t; g_pos[t] = p; }
        cb += __popc(cm);
        nb += __popc(nm);
    }
    if (lane == 0) { g_cnt[0] = cb; g_cnt[1] = nb; }
}

__global__ void t4_kernel(const float* __restrict__ x, const float* __restrict__ u4) {
    int warp = threadIdx.x >> 5, lane = threadIdx.x & 31;
    int t = blockIdx.x * 8 + warp;
    float a0 = 0.f, a1 = 0.f, a2 = 0.f, a3 = 0.f;
    const float* xr = x + (size_t)t * HH;
    for (int k = lane; k < HH; k += 32) {
        float xv = xr[k];
        a0 += xv * u4[k];
        a1 += xv * u4[HH + k];
        a2 += xv * u4[2 * HH + k];
        a3 += xv * u4[3 * HH + k];
    }
    #pragma unroll
    for (int o = 16; o > 0; o >>= 1) {
        a0 += __shfl_xor_sync(0xffffffffu, a0, o);
        a1 += __shfl_xor_sync(0xffffffffu, a1, o);
        a2 += __shfl_xor_sync(0xffffffffu, a2, o);
        a3 += __shfl_xor_sync(0xffffffffu, a3, o);
    }
    if (lane == 0) {
        g_T4[t * 4 + 0] = a0;
        g_T4[t * 4 + 1] = a1;
        g_T4[t * 4 + 2] = a2;
        g_T4[t * 4 + 3] = a3;
    }
}

__device__ __forceinline__ float4 f4add(float4 a, float4 b) {
    return make_float4(a.x + b.x, a.y + b.y, a.z + b.z, a.w + b.w);
}

__global__ __launch_bounds__(256) void final_kernel(const float* __restrict__ x,
                                                    const float* __restrict__ deltas,
                                                    const float* __restrict__ v4,
                                                    float* __restrict__ out) {
    int t = blockIdx.x;
    int tid = threadIdx.x;
    int crit = g_crit[t], simp = g_simp[t];
    const float4* x4 = (const float4*)(x + (size_t)t * HH);
    float4* o4 = (float4*)(out + (size_t)t * HH);

    if (crit) {
        const float4* y4 = (const float4*)(g_Y + (size_t)g_pos[t] * HH);
        #pragma unroll
        for (int r = 0; r < 2; r++) {
            int i = r * 256 + tid;
            o4[i] = y4[i];
        }
    } else if (simp) {
        if (g_flags[1]) {
            const float4* d4 = (const float4*)(deltas + (size_t)g_flags[0] * TT * HH + (size_t)t * HH);
            #pragma unroll
            for (int r = 0; r < 2; r++) {
                int i = r * 256 + tid;
                o4[i] = f4add(x4[i], d4[i]);
            }
        } else {
            float t0 = g_T4[t * 4 + 0], t1 = g_T4[t * 4 + 1];
            float t2 = g_T4[t * 4 + 2], t3 = g_T4[t * 4 + 3];
            const float4* v44 = (const float4*)v4;
            #pragma unroll
            for (int r = 0; r < 2; r++) {
                int i = r * 256 + tid;
                int h = i * 4;
                float4 xv = x4[i];
                float lr[4];
                #pragma unroll
                for (int j = 0; j < 4; j++) {
                    float4 vr = v44[h + j];
                    lr[j] = t0 * vr.x + t1 * vr.y + t2 * vr.z + t3 * vr.w;
                }
                o4[i] = make_float4(xv.x + lr[0], xv.y + lr[1], xv.z + lr[2], xv.w + lr[3]);
            }
        }
    } else {
        const float4* l4 = (const float4*)(g_Lsel + (size_t)g_pos[t] * HH);
        #pragma unroll
        for (int r = 0; r < 2; r++) {
            int i = r * 256 + tid;
            o4[i] = f4add(x4[i], l4[i]);
        }
    }
}

// =================== launch ===================
extern "C" void kernel_launch(void* const* d_in, const int* in_sizes, int n_in,
                              void* d_out, int out_size) {
    const float* x          = (const float*)d_in[0];
    const float* scorer_w1  = (const float*)d_in[1];
    const float* scorer_b1  = (const float*)d_in[2];
    const float* scorer_w2  = (const float*)d_in[3];
    const float* scorer_b2  = (const float*)d_in[4];
    const float* pos_imp    = (const float*)d_in[5];
    const float* key_proj_w = (const float*)d_in[6];
    const float* cache_keys = (const float*)d_in[7];
    const float* cache_del  = (const float*)d_in[8];
    const float* ce_w1      = (const float*)d_in[9];
    const float* ce_b1      = (const float*)d_in[10];
    const float* ce_w2      = (const float*)d_in[11];
    const float* ce_b2      = (const float*)d_in[12];
    const float* u4   = (const float*)d_in[13];
    const float* v4   = (const float*)d_in[14];
    const float* u12  = (const float*)d_in[15];
    const float* v12  = (const float*)d_in[16];
    const float* u40  = (const float*)d_in[17];
    const float* v40  = (const float*)d_in[18];
    const float* u128 = (const float*)d_in[19];
    const float* v128 = (const float*)d_in[20];
    const float* layer_w = (const float*)d_in[21];
    const float* layer_b = (const float*)d_in[22];
    float* out = (float*)d_out;

    float* d_hP; cudaGetSymbolAddress((void**)&d_hP, g_hP);
    float* d_Y;  cudaGetSymbolAddress((void**)&d_Y, g_Y);

    // 1) pooled partial sums
    pool_part<<<dim3(16, 8), 256>>>(x);
    // 2) fused pool-reduce + dots + cache/rank selection (+nflag reset)
    prep_kernel<<<1, 1024>>>(key_proj_w, ce_w1, ce_b1, cache_keys, ce_w2, ce_b2);
    // 3) scorer GEMM (bf16 3x), split-K x2
    g_scorer<<<dim3(16, 4, 2), 256, SMEM_BF>>>(x, scorer_w1, d_hP);
    // 4) importance + masks + near-threshold flags
    imp_kernel<<<256, 256>>>(scorer_w2, scorer_b2, scorer_b1, pos_imp);
    // 5) fp32 recheck of near-threshold tokens
    recheck_kernel<<<64, 256>>>(x, scorer_w1, scorer_b1, scorer_w2, scorer_b2, pos_imp);
    // 6) compaction
    compact_kernel<<<1, 32>>>();
    // 7) layer GEMM on critical tokens (bf16 3x)
    g_layer<<<dim3(16, 16), 256, SMEM_BF>>>(x, layer_w, layer_b, d_Y);
    // 8) T4 (simple-miss path)
    t4_kernel<<<256, 256>>>(x, u4);
    // 9) Tsel on normal tokens (bf16 3x), split-K x32, then reduce
    g_tsel<<<dim3(16, 1, NSPLIT_T), 256, SMEM_BF>>>(x, u4, u12, u40, u128);
    tsel_reduce<<<TT * 128 / 256, 256>>>();
    // 10) Lsel on normal tokens (bf16 3x)
    g_lsel<<<dim3(16, 16), 256, SMEM_BF>>>(v4, v12, v40, v128);
    // 11) route per token
    final_kernel<<<TT, 256>>>(x, cache_del, v4, out);
}

// round 7
// speedup vs baseline: 4.4186x; 1.0704x over previous
#include <cuda_runtime.h>
#include <cuda_bf16.h>
#include <cstdint>
#include <math.h>

// Problem constants
#define BB 2
#define SS 1024
#define HH 2048
#define TT (BB*SS)      // 2048 tokens
#define F1 512          // H/4
#define KD 32
#define NCACHE 16
#define CEH 64
#define NSPLIT_T 32     // tsel split-K factor

// ---------------- scratch (static device memory; no allocations) ----------------
__device__ float g_hP[2 * TT * F1];          // scorer split-K partials
__device__ float g_Y[TT * HH];               // layer output (compact critical rows)
__device__ float g_Lsel[TT * HH];            // low-rank update (compact normal rows)
__device__ float g_Tsel[TT * 128];           // compact normal rows @ Usel^T
__device__ float g_TselP[NSPLIT_T * TT * 128];
__device__ float g_pp[8 * BB * HH];
__device__ unsigned char g_crit[TT];
__device__ unsigned char g_simp[TT];
__device__ int g_cidx[TT];
__device__ int g_nidx[TT];
__device__ int g_pos[TT];
__device__ int g_cnt[2];
__device__ int g_flags[4];
__device__ int g_nflag;                      // near-threshold token count
__device__ int g_flist[64];                  // near-threshold token list

// z-space mask thresholds (sigmoid-equivalent)
#define ZC_NORM  1.3862944f    // sigmoid(z)>0.8
#define ZS_NORM (-0.8472979f)  // sigmoid(z)<0.3
#define ZC_EDGE (-0.4054651f)  // 2*sigmoid(z)>0.8
#define ZS_EDGE (-1.7346011f)  // 2*sigmoid(z)<0.3
#define Z_GUARD  2e-3f

// =================== conversion helpers ===================
__device__ __forceinline__ void f2bf2(float x, float y, uint32_t& hi, uint32_t& lo) {
    __nv_bfloat162 h = __floats2bfloat162_rn(x, y);
    float rx = x - __bfloat162float(h.x);
    float ry = y - __bfloat162float(h.y);
    __nv_bfloat162 l = __floats2bfloat162_rn(rx, ry);
    hi = *(uint32_t*)&h;
    lo = *(uint32_t*)&l;
}

#define MMA16(c, a0, a1, a2, a3, b0, b1) \
    asm volatile("mma.sync.aligned.m16n8k16.row.col.f32.bf16.bf16.f32 " \
                 "{%0,%1,%2,%3},{%4,%5,%6,%7},{%8,%9},{%0,%1,%2,%3};" \
                 : "+f"((c)[0]), "+f"((c)[1]), "+f"((c)[2]), "+f"((c)[3]) \
                 : "r"(a0), "r"(a1), "r"(a2), "r"(a3), "r"(b0), "r"(b1))

// =================== bf16 3x GEMM (m16n8k16): C = A @ B^T ===================
// CTA tile 128x128, BK=32 (2 ksteps), 8 warps (4Mx2N), warp 32x64.
#define LDPB 20
#define SMEM_BF (4 * 128 * LDPB * 4)   // 40 KB

template <int EPI>   // 0 none, 1 +bias
__device__ void bf16_gemm_body(const float* __restrict__ A, int lda,
                               const int* __restrict__ aidx,
                               const int* __restrict__ mcnt, int Mstat,
                               const float* __restrict__ B, int ldb, int Nb,
                               const float* __restrict__ bias,
                               float* __restrict__ C, int ldc, int Ncols,
                               int K, int kt_begin, int kt_end) {
    extern __shared__ uint32_t smem_u[];
    uint32_t* AHI = smem_u;
    uint32_t* ALO = smem_u + 128 * LDPB;
    uint32_t* BHI = smem_u + 2 * 128 * LDPB;
    uint32_t* BLO = smem_u + 3 * 128 * LDPB;

    int M = mcnt ? *mcnt : Mstat;
    int bm = blockIdx.x * 128, bn = blockIdx.y * 128;
    if (bm >= M) return;

    int tid = threadIdx.x, wid = tid >> 5, lane = tid & 31;
    int wm = wid & 3, wn = wid >> 2;
    int group = lane >> 2, tg = lane & 3;

    const float* apt[4];
    const float* bpt[4];
    int rowv[4], kcv[4];
    #pragma unroll
    for (int i = 0; i < 4; i++) {
        int f = tid + i * 256;
        int row = f >> 3, kc = (f & 7) * 4;
        rowv[i] = row; kcv[i] = kc;
        int ar = bm + row;
        apt[i] = (ar < M) ? (A + (size_t)(aidx ? aidx[ar] : ar) * lda + kc) : nullptr;
        int br = bn + row;
        bpt[i] = (br < Nb) ? (B + (size_t)br * ldb + kc) : nullptr;
    }

    float acc[2][8][4];
    #pragma unroll
    for (int mi = 0; mi < 2; mi++)
        #pragma unroll
        for (int ni = 0; ni < 8; ni++)
            #pragma unroll
            for (int q = 0; q < 4; q++) acc[mi][ni][q] = 0.f;

    float4 ra[4], rb[4];
    {
        int k0 = kt_begin * 32;
        #pragma unroll
        for (int i = 0; i < 4; i++) {
            int gk = k0 + kcv[i];
            float4 z = make_float4(0.f, 0.f, 0.f, 0.f);
            ra[i] = (apt[i] && gk < K) ? *(const float4*)(apt[i] + k0) : z;
            rb[i] = (bpt[i] && gk < K) ? *(const float4*)(bpt[i] + k0) : z;
        }
    }

    for (int kt = kt_begin; kt < kt_end; kt++) {
        __syncthreads();
        #pragma unroll
        for (int i = 0; i < 4; i++) {
            int off = rowv[i] * LDPB + (kcv[i] >> 1);
            uint2 h, l;
            f2bf2(ra[i].x, ra[i].y, h.x, l.x);
            f2bf2(ra[i].z, ra[i].w, h.y, l.y);
            *(uint2*)(AHI + off) = h;
            *(uint2*)(ALO + off) = l;
            f2bf2(rb[i].x, rb[i].y, h.x, l.x);
            f2bf2(rb[i].z, rb[i].w, h.y, l.y);
            *(uint2*)(BHI + off) = h;
            *(uint2*)(BLO + off) = l;
        }
        __syncthreads();

        if (kt + 1 < kt_end) {
            int k0 = (kt + 1) * 32;
            #pragma unroll
            for (int i = 0; i < 4; i++) {
                int gk = k0 + kcv[i];
                float4 z = make_float4(0.f, 0.f, 0.f, 0.f);
                ra[i] = (apt[i] && gk < K) ? *(const float4*)(apt[i] + k0) : z;
                rb[i] = (bpt[i] && gk < K) ? *(const float4*)(bpt[i] + k0) : z;
            }
        }

        #pragma unroll
        for (int ks = 0; ks < 2; ks++) {
            int kb = ks * 8 + tg;
            uint32_t ah[2][4], al[2][4];
            #pragma unroll
            for (int mi = 0; mi < 2; mi++) {
                int r0 = (wm * 32 + mi * 16 + group) * LDPB;
                ah[mi][0] = AHI[r0 + kb];
                ah[mi][1] = AHI[r0 + 8 * LDPB + kb];
                ah[mi][2] = AHI[r0 + kb + 4];
                ah[mi][3] = AHI[r0 + 8 * LDPB + kb + 4];
                al[mi][0] = ALO[r0 + kb];
                al[mi][1] = ALO[r0 + 8 * LDPB + kb];
                al[mi][2] = ALO[r0 + kb + 4];
                al[mi][3] = ALO[r0 + 8 * LDPB + kb + 4];
            }
            #pragma unroll
            for (int ni = 0; ni < 8; ni++) {
                int nr = (wn * 64 + ni * 8 + group) * LDPB;
                uint32_t bh0 = BHI[nr + kb], bh1 = BHI[nr + kb + 4];
                uint32_t bl0 = BLO[nr + kb], bl1 = BLO[nr + kb + 4];
                #pragma unroll
                for (int mi = 0; mi < 2; mi++) {
                    MMA16(acc[mi][ni], ah[mi][0], ah[mi][1], ah[mi][2], ah[mi][3], bh0, bh1);
                    MMA16(acc[mi][ni], ah[mi][0], ah[mi][1], ah[mi][2], ah[mi][3], bl0, bl1);
                    MMA16(acc[mi][ni], al[mi][0], al[mi][1], al[mi][2], al[mi][3], bh0, bh1);
                }
            }
        }
    }

    #pragma unroll
    for (int mi = 0; mi < 2; mi++) {
        int r0 = bm + wm * 32 + mi * 16 + group;
        #pragma unroll
        for (int ni = 0; ni < 8; ni++) {
            int col = bn + wn * 64 + ni * 8 + 2 * tg;
            if (col >= Ncols) continue;
            float b0 = 0.f, b1 = 0.f;
            if (EPI == 1) { b0 = bias[col]; b1 = bias[col + 1]; }
            if (r0 < M)
                *(float2*)(C + (size_t)r0 * ldc + col) =
                    make_float2(acc[mi][ni][0] + b0, acc[mi][ni][1] + b1);
            if (r0 + 8 < M)
                *(float2*)(C + (size_t)(r0 + 8) * ldc + col) =
                    make_float2(acc[mi][ni][2] + b0, acc[mi][ni][3] + b1);
        }
    }
}

__global__ __launch_bounds__(256, 1) void g_scorer(const float* x, const float* w1,
                                                   float* C) {
    int z = blockIdx.z;
    bf16_gemm_body<0>(x, HH, nullptr, nullptr, TT, w1, HH, F1, nullptr,
                      C + (size_t)z * TT * F1, F1, F1, HH, z * 32, z * 32 + 32);
}

__global__ __launch_bounds__(256, 1) void g_layer(const float* x, const float* w,
                                                  const float* b, float* C) {
    bf16_gemm_body<1>(x, HH, g_cidx, &g_cnt[0], 0, w, HH, HH, b, C, HH, HH, HH, 0, 64);
}

__global__ __launch_bounds__(256, 1) void g_tsel(const float* x,
                                                 const float* u4, const float* u12,
                                                 const float* u40, const float* u128) {
    int ri = g_flags[2], rv = g_flags[3];
    const float* U = (ri == 0) ? u4 : (ri == 1) ? u12 : (ri == 2) ? u40 : u128;
    int z = blockIdx.z;
    bf16_gemm_body<0>(x, HH, g_nidx, &g_cnt[1], 0, U, HH, rv, nullptr,
                      g_TselP + (size_t)z * TT * 128, 128, 128, HH, z * 2, z * 2 + 2);
}

__global__ void tsel_reduce() {
    int n = g_cnt[1] * 128;
    int i = blockIdx.x * 256 + threadIdx.x;
    if (i >= n) return;
    float s = 0.f;
    #pragma unroll
    for (int z = 0; z < NSPLIT_T; z++) s += g_TselP[(size_t)z * TT * 128 + i];
    g_Tsel[i] = s;
}

__global__ __launch_bounds__(256, 1) void g_lsel(const float* v4, const float* v12,
                                                 const float* v40, const float* v128) {
    int ri = g_flags[2], rv = g_flags[3];
    const float* V = (ri == 0) ? v4 : (ri == 1) ? v12 : (ri == 2) ? v40 : v128;
    bf16_gemm_body<0>(g_Tsel, 128, nullptr, &g_cnt[1], 0, V, rv, HH, nullptr,
                      g_Lsel, HH, HH, rv, 0, (rv + 31) / 32);
}

// =================== small kernels ===================
__global__ void pool_part(const float* __restrict__ x) {
    int i = blockIdx.x * 256 + threadIdx.x;
    int b = i / HH, h = i % HH;
    int c = blockIdx.y;
    const float* p = x + ((size_t)b * SS + (size_t)c * 128) * HH + h;
    float s0 = 0.f, s1 = 0.f, s2 = 0.f, s3 = 0.f;
    #pragma unroll 8
    for (int s = 0; s < 128; s += 4) {
        s0 += p[(size_t)s * HH];
        s1 += p[(size_t)(s + 1) * HH];
        s2 += p[(size_t)(s + 2) * HH];
        s3 += p[(size_t)(s + 3) * HH];
    }
    g_pp[c * BB * HH + i] = s0 + s1 + s2 + s3;
}

// fused: pool_reduce + dots + cache/rank selection + recheck-counter reset
__global__ __launch_bounds__(1024) void prep_kernel(const float* __restrict__ key_proj_w,
                                                    const float* __restrict__ ce_w1,
                                                    const float* __restrict__ ce_b1,
                                                    const float* __restrict__ cache_keys,
                                                    const float* __restrict__ ce_w2,
                                                    const float* __restrict__ ce_b2) {
    __shared__ float pooled[BB * HH];     // 16 KB
    __shared__ float qk_s[64];
    __shared__ float qfn[64];
    __shared__ float ceh[2 * CEH];
    __shared__ float sims[16];
    __shared__ float scores[8];
    __shared__ float s_qnorm;
    int tid = threadIdx.x, warp = tid >> 5, lane = tid & 31;

    if (tid == 0) g_nflag = 0;

    for (int i = tid; i < BB * HH; i += 1024) {
        float s = 0.f;
        #pragma unroll
        for (int c = 0; c < 8; c++) s += g_pp[c * BB * HH + i];
        pooled[i] = s * (1.0f / SS);
    }
    __syncthreads();

    for (int c = 0; c < 6; c++) {
        int j = warp + 32 * c;
        const float* pl;
        const float* w;
        if (j < 64) {
            pl = pooled + (j / KD) * HH;
            w = key_proj_w + (size_t)(j % KD) * HH;
        } else {
            int jj = j - 64;
            pl = pooled + (jj / CEH) * HH;
            w = ce_w1 + (size_t)(jj % CEH) * HH;
        }
        float s = 0.f;
        for (int k = lane; k < HH; k += 32) s += pl[k] * w[k];
        #pragma unroll
        for (int o = 16; o > 0; o >>= 1) s += __shfl_xor_sync(0xffffffffu, s, o);
        if (lane == 0) {
            if (j < 64) qk_s[j] = s;
            else {
                int jj = j - 64;
                ceh[jj] = fmaxf(s + ce_b1[jj % CEH], 0.f);
            }
        }
    }
    __syncthreads();

    if (warp < 2) {
        float v = qk_s[warp * 32 + lane];
        float s = v * v;
        #pragma unroll
        for (int o = 16; o > 0; o >>= 1) s += __shfl_xor_sync(0xffffffffu, s, o);
        qfn[warp * 32 + lane] = v * (1.0f / fmaxf(sqrtf(s), 1e-8f));
    }
    if (warp >= 8 && warp < 16) {
        int w8 = warp - 8;
        int b = w8 >> 2, r = w8 & 3;
        float s = ceh[b * CEH + lane] * ce_w2[r * CEH + lane]
                + ceh[b * CEH + 32 + lane] * ce_w2[r * CEH + 32 + lane];
        #pragma unroll
        for (int o = 16; o > 0; o >>= 1) s += __shfl_xor_sync(0xffffffffu, s, o);
        if (lane == 0) scores[w8] = s + ce_b2[r];
    }
    __syncthreads();
    if (tid < 32) {
        float s = qfn[tid] * qfn[tid] + qfn[32 + tid] * qfn[32 + tid];
        #pragma unroll
        for (int o = 16; o > 0; o >>= 1) s += __shfl_xor_sync(0xffffffffu, s, o);
        if (tid == 0) s_qnorm = sqrtf(s);
    }
    __syncthreads();
    if (tid < 256) {
        int e = tid >> 4, sub = tid & 15;
        float d = 0.f, n = 0.f;
        #pragma unroll
        for (int i = 0; i < 4; i++) {
            float c = cache_keys[e * 64 + sub * 4 + i];
            d += c * qfn[sub * 4 + i];
            n += c * c;
        }
        #pragma unroll
        for (int o = 8; o > 0; o >>= 1) {
            d += __shfl_xor_sync(0xffffffffu, d, o);
            n += __shfl_xor_sync(0xffffffffu, n, o);
        }
        if (sub == 0)
            sims[e] = d / (fmaxf(sqrtf(n), 1e-8f) * fmaxf(s_qnorm, 1e-8f));
    }
    __syncthreads();
    if (tid == 0) {
        int best = 0;
        float bv = sims[0];
        for (int n = 1; n < NCACHE; n++)
            if (sims[n] > bv) { bv = sims[n]; best = n; }
        g_flags[0] = best;
        g_flags[1] = (bv >= 0.95f) ? 1 : 0;
        int bi = 0;
        float sv = scores[0];
        for (int i = 1; i < 8; i++)
            if (scores[i] > sv) { sv = scores[i]; bi = i; }
        int ri = bi % 4;
        g_flags[2] = ri;
        g_flags[3] = (ri == 0) ? 4 : (ri == 1) ? 12 : (ri == 2) ? 40 : 128;
    }
}

// importance: fused bias+relu+dot over scorer partials (float4-vectorized)
__global__ void imp_kernel(const float* __restrict__ w2,
                           const float* __restrict__ b2,
                           const float* __restrict__ b1,
                           const float* __restrict__ pos) {
    int warp = threadIdx.x >> 5, lane = threadIdx.x & 31;
    int t = blockIdx.x * 8 + warp;
    const float4* p0 = (const float4*)(g_hP + (size_t)t * F1);
    const float4* p1 = (const float4*)(g_hP + (size_t)TT * F1 + (size_t)t * F1);
    const float4* b14 = (const float4*)b1;
    const float4* w24 = (const float4*)w2;
    float s = 0.f;
    #pragma unroll
    for (int it = 0; it < 4; it++) {
        int f = lane + it * 32;              // float4 index, 128 per row
        float4 a = p0[f], b = p1[f], bb = b14[f], w = w24[f];
        s += fmaxf(a.x + b.x + bb.x, 0.f) * w.x;
        s += fmaxf(a.y + b.y + bb.y, 0.f) * w.y;
        s += fmaxf(a.z + b.z + bb.z, 0.f) * w.z;
        s += fmaxf(a.w + b.w + bb.w, 0.f) * w.w;
    }
    #pragma unroll
    for (int o = 16; o > 0; o >>= 1) s += __shfl_xor_sync(0xffffffffu, s, o);
    if (lane == 0) {
        int spos = t % SS;
        float z = s + b2[0] + 0.1f * pos[spos];
        bool edge = (spos == 0 || spos == SS - 1);
        float zc = edge ? ZC_EDGE : ZC_NORM;
        float zs = edge ? ZS_EDGE : ZS_NORM;
        g_crit[t] = (z > zc) ? 1 : 0;
        g_simp[t] = (z < zs) ? 1 : 0;
        if (fabsf(z - zc) < Z_GUARD || fabsf(z - zs) < Z_GUARD) {
            int i = atomicAdd(&g_nflag, 1);
            if (i < 64) g_flist[i] = t;
        }
    }
}

// fp32 recheck of near-threshold tokens (block per flagged token)
__global__ __launch_bounds__(256) void recheck_kernel(const float* __restrict__ x,
                                                      const float* __restrict__ w1,
                                                      const float* __restrict__ b1,
                                                      const float* __restrict__ w2,
                                                      const float* __restrict__ b2,
                                                      const float* __restrict__ pos) {
    int nf = g_nflag; if (nf > 64) nf = 64;
    if ((int)blockIdx.x >= nf) return;
    int t = g_flist[blockIdx.x];

    __shared__ float xs[HH];
    __shared__ float ws[8];
    int tid = threadIdx.x, warp = tid >> 5, lane = tid & 31;
    for (int k = tid; k < HH; k += 256) xs[k] = x[(size_t)t * HH + k];
    __syncthreads();

    float s = 0.f;
    for (int i = 0; i < F1 / 8; i++) {
        int j = warp + i * 8;
        const float* wr = w1 + (size_t)j * HH;
        float d = 0.f;
        for (int k = lane; k < HH; k += 32) d += xs[k] * wr[k];
        #pragma unroll
        for (int o = 16; o > 0; o >>= 1) d += __shfl_xor_sync(0xffffffffu, d, o);
        s += fmaxf(d + b1[j], 0.f) * w2[j];
    }
    if (lane == 0) ws[warp] = s;
    __syncthreads();
    if (tid == 0) {
        float z = b2[0];
        #pragma unroll
        for (int w = 0; w < 8; w++) z += ws[w];
        int spos = t % SS;
        z += 0.1f * pos[spos];
        bool edge = (spos == 0 || spos == SS - 1);
        float zc = edge ? ZC_EDGE : ZC_NORM;
        float zs = edge ? ZS_EDGE : ZS_NORM;
        g_crit[t] = (z > zc) ? 1 : 0;
        g_simp[t] = (z < zs) ? 1 : 0;
    }
}

__global__ void compact_kernel() {
    int lane = threadIdx.x;
    int cb = 0, nb = 0;
    for (int it = 0; it < TT / 32; it++) {
        int t = it * 32 + lane;
        int c = g_crit[t], s = g_simp[t];
        int nn = !(c || s);
        unsigned cm = __ballot_sync(0xffffffffu, c);
        unsigned nm = __ballot_sync(0xffffffffu, nn);
        unsigned lt = (1u << lane) - 1u;
        if (c) { int p = cb + __popc(cm & lt); g_cidx[p] = t; g_pos[t] = p; }
        if (nn) { int p = nb + __popc(nm & lt); g_nidx[p] = t; g_pos[t] = p; }
        cb += __popc(cm);
        nb += __popc(nm);
    }
    if (lane == 0) { g_cnt[0] = cb; g_cnt[1] = nb; }
}

__device__ __forceinline__ float4 f4add(float4 a, float4 b) {
    return make_float4(a.x + b.x, a.y + b.y, a.z + b.z, a.w + b.w);
}

// final routed epilogue; rank-4 fallback (simple-miss) computed in-place
__global__ __launch_bounds__(256) void final_kernel(const float* __restrict__ x,
                                                    const float* __restrict__ deltas,
                                                    const float* __restrict__ u4,
                                                    const float* __restrict__ v4,
                                                    float* __restrict__ out) {
    int t = blockIdx.x;
    int tid = threadIdx.x;
    int crit = g_crit[t], simp = g_simp[t];
    const float4* x4 = (const float4*)(x + (size_t)t * HH);
    float4* o4 = (float4*)(out + (size_t)t * HH);

    if (crit) {
        const float4* y4 = (const float4*)(g_Y + (size_t)g_pos[t] * HH);
        #pragma unroll
        for (int r = 0; r < 2; r++) {
            int i = r * 256 + tid;
            o4[i] = y4[i];
        }
    } else if (simp) {
        if (g_flags[1]) {
            const float4* d4 = (const float4*)(deltas + (size_t)g_flags[0] * TT * HH + (size_t)t * HH);
            #pragma unroll
            for (int r = 0; r < 2; r++) {
                int i = r * 256 + tid;
                o4[i] = f4add(x4[i], d4[i]);
            }
        } else {
            // fused T4 = x_row @ u4^T (block reduce, fixed order -> deterministic)
            __shared__ float red[8][4];
            __shared__ float tvals[4];
            int warp = tid >> 5, lane = tid & 31;
            float a0 = 0.f, a1 = 0.f, a2 = 0.f, a3 = 0.f;
            float4 xv_c[2];
            #pragma unroll
            for (int r = 0; r < 2; r++) {
                int i = r * 256 + tid;       // float4 index, h = 4*i
                float4 xv = x4[i];
                xv_c[r] = xv;
                const float4 u0 = *(const float4*)(u4 + 0 * HH + i * 4);
                const float4 u1 = *(const float4*)(u4 + 1 * HH + i * 4);
                const float4 u2 = *(const float4*)(u4 + 2 * HH + i * 4);
                const float4 u3 = *(const float4*)(u4 + 3 * HH + i * 4);
                a0 += xv.x * u0.x + xv.y * u0.y + xv.z * u0.z + xv.w * u0.w;
                a1 += xv.x * u1.x + xv.y * u1.y + xv.z * u1.z + xv.w * u1.w;
                a2 += xv.x * u2.x + xv.y * u2.y + xv.z * u2.z + xv.w * u2.w;
                a3 += xv.x * u3.x + xv.y * u3.y + xv.z * u3.z + xv.w * u3.w;
            }
            #pragma unroll
            for (int o = 16; o > 0; o >>= 1) {
                a0 += __shfl_xor_sync(0xffffffffu, a0, o);
                a1 += __shfl_xor_sync(0xffffffffu, a1, o);
                a2 += __shfl_xor_sync(0xffffffffu, a2, o);
                a3 += __shfl_xor_sync(0xffffffffu, a3, o);
            }
            if (lane == 0) {
                red[warp][0] = a0; red[warp][1] = a1;
                red[warp][2] = a2; red[warp][3] = a3;
            }
            __syncthreads();
            if (tid < 4) {
                float s = 0.f;
                #pragma unroll
                for (int w = 0; w < 8; w++) s += red[w][tid];
                tvals[tid] = s;
            }
            __syncthreads();
            float t0 = tvals[0], t1 = tvals[1], t2 = tvals[2], t3 = tvals[3];
            const float4* v44 = (const float4*)v4;
            #pragma unroll
            for (int r = 0; r < 2; r++) {
                int i = r * 256 + tid;
                int h = i * 4;
                float4 xv = xv_c[r];
                float lr[4];
                #pragma unroll
                for (int j = 0; j < 4; j++) {
                    float4 vr = v44[h + j];
                    lr[j] = t0 * vr.x + t1 * vr.y + t2 * vr.z + t3 * vr.w;
                }
                o4[i] = make_float4(xv.x + lr[0], xv.y + lr[1], xv.z + lr[2], xv.w + lr[3]);
            }
        }
    } else {
        const float4* l4 = (const float4*)(g_Lsel + (size_t)g_pos[t] * HH);
        #pragma unroll
        for (int r = 0; r < 2; r++) {
            int i = r * 256 + tid;
            o4[i] = f4add(x4[i], l4[i]);
        }
    }
}

// =================== launch ===================
extern "C" void kernel_launch(void* const* d_in, const int* in_sizes, int n_in,
                              void* d_out, int out_size) {
    const float* x          = (const float*)d_in[0];
    const float* scorer_w1  = (const float*)d_in[1];
    const float* scorer_b1  = (const float*)d_in[2];
    const float* scorer_w2  = (const float*)d_in[3];
    const float* scorer_b2  = (const float*)d_in[4];
    const float* pos_imp    = (const float*)d_in[5];
    const float* key_proj_w = (const float*)d_in[6];
    const float* cache_keys = (const float*)d_in[7];
    const float* cache_del  = (const float*)d_in[8];
    const float* ce_w1      = (const float*)d_in[9];
    const float* ce_b1      = (const float*)d_in[10];
    const float* ce_w2      = (const float*)d_in[11];
    const float* ce_b2      = (const float*)d_in[12];
    const float* u4   = (const float*)d_in[13];
    const float* v4   = (const float*)d_in[14];
    const float* u12  = (const float*)d_in[15];
    const float* v12  = (const float*)d_in[16];
    const float* u40  = (const float*)d_in[17];
    const float* v40  = (const float*)d_in[18];
    const float* u128 = (const float*)d_in[19];
    const float* v128 = (const float*)d_in[20];
    const float* layer_w = (const float*)d_in[21];
    const float* layer_b = (const float*)d_in[22];
    float* out = (float*)d_out;

    float* d_hP; cudaGetSymbolAddress((void**)&d_hP, g_hP);
    float* d_Y;  cudaGetSymbolAddress((void**)&d_Y, g_Y);

    // 1) pooled partial sums
    pool_part<<<dim3(16, 8), 256>>>(x);
    // 2) fused pool-reduce + dots + cache/rank selection (+nflag reset)
    prep_kernel<<<1, 1024>>>(key_proj_w, ce_w1, ce_b1, cache_keys, ce_w2, ce_b2);
    // 3) scorer GEMM (bf16 3x), split-K x2
    g_scorer<<<dim3(16, 4, 2), 256, SMEM_BF>>>(x, scorer_w1, d_hP);
    // 4) importance + masks + near-threshold flags (vectorized)
    imp_kernel<<<256, 256>>>(scorer_w2, scorer_b2, scorer_b1, pos_imp);
    // 5) fp32 recheck of near-threshold tokens
    recheck_kernel<<<64, 256>>>(x, scorer_w1, scorer_b1, scorer_w2, scorer_b2, pos_imp);
    // 6) compaction
    compact_kernel<<<1, 32>>>();
    // 7) layer GEMM on critical tokens (bf16 3x)
    g_layer<<<dim3(16, 16), 256, SMEM_BF>>>(x, layer_w, layer_b, d_Y);
    // 8) Tsel on normal tokens (bf16 3x), split-K x32, then reduce
    g_tsel<<<dim3(16, 1, NSPLIT_T), 256, SMEM_BF>>>(x, u4, u12, u40, u128);
    tsel_reduce<<<TT * 128 / 256, 256>>>();
    // 9) Lsel on normal tokens (bf16 3x)
    g_lsel<<<dim3(16, 16), 256, SMEM_BF>>>(v4, v12, v40, v128);
    // 10) route per token (rank-4 fallback fused)
    final_kernel<<<TT, 256>>>(x, cache_del, u4, v4, out);
}

// round 8
// speedup vs baseline: 5.2579x; 1.1899x over previous
#include <cuda_runtime.h>
#include <cuda_bf16.h>
#include <cstdint>
#include <math.h>

// Problem constants
#define BB 2
#define SS 1024
#define HH 2048
#define TT (BB*SS)      // 2048 tokens
#define F1 512          // H/4
#define KD 32
#define NCACHE 16
#define CEH 64
#define NSPLIT_T 32     // tsel split-K factor

// ---------------- scratch (static device memory; no allocations) ----------------
__device__ float g_hP[2 * TT * F1];          // scorer split-K partials
__device__ float g_Y[TT * HH];               // layer output (compact critical rows)
__device__ float g_Lsel[TT * HH];            // low-rank update (compact normal rows)
__device__ float g_Tsel[TT * 128];           // compact normal rows @ Usel^T
__device__ float g_TselP[NSPLIT_T * TT * 128];
__device__ float g_pp[8 * BB * HH];
__device__ unsigned char g_crit[TT];
__device__ unsigned char g_simp[TT];
__device__ int g_cidx[TT];
__device__ int g_nidx[TT];
__device__ int g_pos[TT];
__device__ int g_cnt[2];
__device__ int g_flags[4];
__device__ int g_nflag;                      // near-threshold token count
__device__ int g_flist[64];                  // near-threshold token list
__device__ int g_done;                       // last-block counter (self-resetting)

// z-space mask thresholds (sigmoid-equivalent)
#define ZC_NORM  1.3862944f    // sigmoid(z)>0.8
#define ZS_NORM (-0.8472979f)  // sigmoid(z)<0.3
#define ZC_EDGE (-0.4054651f)  // 2*sigmoid(z)>0.8
#define ZS_EDGE (-1.7346011f)  // 2*sigmoid(z)<0.3
#define Z_GUARD  2e-3f

// =================== conversion helpers ===================
__device__ __forceinline__ void f2bf2(float x, float y, uint32_t& hi, uint32_t& lo) {
    __nv_bfloat162 h = __floats2bfloat162_rn(x, y);
    float rx = x - __bfloat162float(h.x);
    float ry = y - __bfloat162float(h.y);
    __nv_bfloat162 l = __floats2bfloat162_rn(rx, ry);
    hi = *(uint32_t*)&h;
    lo = *(uint32_t*)&l;
}

#define MMA16(c, a0, a1, a2, a3, b0, b1) \
    asm volatile("mma.sync.aligned.m16n8k16.row.col.f32.bf16.bf16.f32 " \
                 "{%0,%1,%2,%3},{%4,%5,%6,%7},{%8,%9},{%0,%1,%2,%3};" \
                 : "+f"((c)[0]), "+f"((c)[1]), "+f"((c)[2]), "+f"((c)[3]) \
                 : "r"(a0), "r"(a1), "r"(a2), "r"(a3), "r"(b0), "r"(b1))

// =================== bf16 3x GEMM (m16n8k16): C = A @ B^T ===================
// CTA tile 128x128, BK=32 (2 ksteps), 8 warps (4Mx2N), warp 32x64.
#define LDPB 20
#define SMEM_BF (4 * 128 * LDPB * 4)   // 40 KB

template <int EPI>   // 0 none, 1 +bias
__device__ void bf16_gemm_body(const float* __restrict__ A, int lda,
                               const int* __restrict__ aidx,
                               const int* __restrict__ mcnt, int Mstat,
                               const float* __restrict__ B, int ldb, int Nb,
                               const float* __restrict__ bias,
                               float* __restrict__ C, int ldc, int Ncols,
                               int K, int kt_begin, int kt_end) {
    extern __shared__ uint32_t smem_u[];
    uint32_t* AHI = smem_u;
    uint32_t* ALO = smem_u + 128 * LDPB;
    uint32_t* BHI = smem_u + 2 * 128 * LDPB;
    uint32_t* BLO = smem_u + 3 * 128 * LDPB;

    int M = mcnt ? *mcnt : Mstat;
    int bm = blockIdx.x * 128, bn = blockIdx.y * 128;
    if (bm >= M) return;

    int tid = threadIdx.x, wid = tid >> 5, lane = tid & 31;
    int wm = wid & 3, wn = wid >> 2;
    int group = lane >> 2, tg = lane & 3;

    const float* apt[4];
    const float* bpt[4];
    int rowv[4], kcv[4];
    #pragma unroll
    for (int i = 0; i < 4; i++) {
        int f = tid + i * 256;
        int row = f >> 3, kc = (f & 7) * 4;
        rowv[i] = row; kcv[i] = kc;
        int ar = bm + row;
        apt[i] = (ar < M) ? (A + (size_t)(aidx ? aidx[ar] : ar) * lda + kc) : nullptr;
        int br = bn + row;
        bpt[i] = (br < Nb) ? (B + (size_t)br * ldb + kc) : nullptr;
    }

    float acc[2][8][4];
    #pragma unroll
    for (int mi = 0; mi < 2; mi++)
        #pragma unroll
        for (int ni = 0; ni < 8; ni++)
            #pragma unroll
            for (int q = 0; q < 4; q++) acc[mi][ni][q] = 0.f;

    float4 ra[4], rb[4];
    {
        int k0 = kt_begin * 32;
        #pragma unroll
        for (int i = 0; i < 4; i++) {
            int gk = k0 + kcv[i];
            float4 z = make_float4(0.f, 0.f, 0.f, 0.f);
            ra[i] = (apt[i] && gk < K) ? *(const float4*)(apt[i] + k0) : z;
            rb[i] = (bpt[i] && gk < K) ? *(const float4*)(bpt[i] + k0) : z;
        }
    }

    for (int kt = kt_begin; kt < kt_end; kt++) {
        __syncthreads();
        #pragma unroll
        for (int i = 0; i < 4; i++) {
            int off = rowv[i] * LDPB + (kcv[i] >> 1);
            uint2 h, l;
            f2bf2(ra[i].x, ra[i].y, h.x, l.x);
            f2bf2(ra[i].z, ra[i].w, h.y, l.y);
            *(uint2*)(AHI + off) = h;
            *(uint2*)(ALO + off) = l;
            f2bf2(rb[i].x, rb[i].y, h.x, l.x);
            f2bf2(rb[i].z, rb[i].w, h.y, l.y);
            *(uint2*)(BHI + off) = h;
            *(uint2*)(BLO + off) = l;
        }
        __syncthreads();

        if (kt + 1 < kt_end) {
            int k0 = (kt + 1) * 32;
            #pragma unroll
            for (int i = 0; i < 4; i++) {
                int gk = k0 + kcv[i];
                float4 z = make_float4(0.f, 0.f, 0.f, 0.f);
                ra[i] = (apt[i] && gk < K) ? *(const float4*)(apt[i] + k0) : z;
                rb[i] = (bpt[i] && gk < K) ? *(const float4*)(bpt[i] + k0) : z;
            }
        }

        #pragma unroll
        for (int ks = 0; ks < 2; ks++) {
            int kb = ks * 8 + tg;
            uint32_t ah[2][4], al[2][4];
            #pragma unroll
            for (int mi = 0; mi < 2; mi++) {
                int r0 = (wm * 32 + mi * 16 + group) * LDPB;
                ah[mi][0] = AHI[r0 + kb];
                ah[mi][1] = AHI[r0 + 8 * LDPB + kb];
                ah[mi][2] = AHI[r0 + kb + 4];
                ah[mi][3] = AHI[r0 + 8 * LDPB + kb + 4];
                al[mi][0] = ALO[r0 + kb];
                al[mi][1] = ALO[r0 + 8 * LDPB + kb];
                al[mi][2] = ALO[r0 + kb + 4];
                al[mi][3] = ALO[r0 + 8 * LDPB + kb + 4];
            }
            #pragma unroll
            for (int ni = 0; ni < 8; ni++) {
                int nr = (wn * 64 + ni * 8 + group) * LDPB;
                uint32_t bh0 = BHI[nr + kb], bh1 = BHI[nr + kb + 4];
                uint32_t bl0 = BLO[nr + kb], bl1 = BLO[nr + kb + 4];
                #pragma unroll
                for (int mi = 0; mi < 2; mi++) {
                    MMA16(acc[mi][ni], ah[mi][0], ah[mi][1], ah[mi][2], ah[mi][3], bh0, bh1);
                    MMA16(acc[mi][ni], ah[mi][0], ah[mi][1], ah[mi][2], ah[mi][3], bl0, bl1);
                    MMA16(acc[mi][ni], al[mi][0], al[mi][1], al[mi][2], al[mi][3], bh0, bh1);
                }
            }
        }
    }

    #pragma unroll
    for (int mi = 0; mi < 2; mi++) {
        int r0 = bm + wm * 32 + mi * 16 + group;
        #pragma unroll
        for (int ni = 0; ni < 8; ni++) {
            int col = bn + wn * 64 + ni * 8 + 2 * tg;
            if (col >= Ncols) continue;
            float b0 = 0.f, b1 = 0.f;
            if (EPI == 1) { b0 = bias[col]; b1 = bias[col + 1]; }
            if (r0 < M)
                *(float2*)(C + (size_t)r0 * ldc + col) =
                    make_float2(acc[mi][ni][0] + b0, acc[mi][ni][1] + b1);
            if (r0 + 8 < M)
                *(float2*)(C + (size_t)(r0 + 8) * ldc + col) =
                    make_float2(acc[mi][ni][2] + b0, acc[mi][ni][3] + b1);
        }
    }
}

__global__ __launch_bounds__(256, 1) void g_scorer(const float* x, const float* w1,
                                                   float* C) {
    // reset recheck counter (imp runs after this kernel on the same stream)
    if (blockIdx.x == 0 && blockIdx.y == 0 && blockIdx.z == 0 && threadIdx.x == 0)
        g_nflag = 0;
    int z = blockIdx.z;
    bf16_gemm_body<0>(x, HH, nullptr, nullptr, TT, w1, HH, F1, nullptr,
                      C + (size_t)z * TT * F1, F1, F1, HH, z * 32, z * 32 + 32);
}

__global__ __launch_bounds__(256, 1) void g_layer(const float* x, const float* w,
                                                  const float* b, float* C) {
    bf16_gemm_body<1>(x, HH, g_cidx, &g_cnt[0], 0, w, HH, HH, b, C, HH, HH, HH, 0, 64);
}

__global__ __launch_bounds__(256, 1) void g_tsel(const float* x,
                                                 const float* u4, const float* u12,
                                                 const float* u40, const float* u128) {
    int ri = g_flags[2], rv = g_flags[3];
    const float* U = (ri == 0) ? u4 : (ri == 1) ? u12 : (ri == 2) ? u40 : u128;
    int z = blockIdx.z;
    bf16_gemm_body<0>(x, HH, g_nidx, &g_cnt[1], 0, U, HH, rv, nullptr,
                      g_TselP + (size_t)z * TT * 128, 128, 128, HH, z * 2, z * 2 + 2);
}

__global__ void tsel_reduce() {
    int n = g_cnt[1] * 128;
    int i = blockIdx.x * 256 + threadIdx.x;
    if (i >= n) return;
    float s = 0.f;
    #pragma unroll
    for (int z = 0; z < NSPLIT_T; z++) s += g_TselP[(size_t)z * TT * 128 + i];
    g_Tsel[i] = s;
}

__global__ __launch_bounds__(256, 1) void g_lsel(const float* v4, const float* v12,
                                                 const float* v40, const float* v128) {
    int ri = g_flags[2], rv = g_flags[3];
    const float* V = (ri == 0) ? v4 : (ri == 1) ? v12 : (ri == 2) ? v40 : v128;
    bf16_gemm_body<0>(g_Tsel, 128, nullptr, &g_cnt[1], 0, V, rv, HH, nullptr,
                      g_Lsel, HH, HH, rv, 0, (rv + 31) / 32);
}

// =================== small kernels ===================
__global__ void pool_part(const float* __restrict__ x) {
    int i = blockIdx.x * 256 + threadIdx.x;
    int b = i / HH, h = i % HH;
    int c = blockIdx.y;
    const float* p = x + ((size_t)b * SS + (size_t)c * 128) * HH + h;
    float s0 = 0.f, s1 = 0.f, s2 = 0.f, s3 = 0.f;
    #pragma unroll 8
    for (int s = 0; s < 128; s += 4) {
        s0 += p[(size_t)s * HH];
        s1 += p[(size_t)(s + 1) * HH];
        s2 += p[(size_t)(s + 2) * HH];
        s3 += p[(size_t)(s + 3) * HH];
    }
    g_pp[c * BB * HH + i] = s0 + s1 + s2 + s3;
}

// fused: pool_reduce + dots + cache/rank selection
__global__ __launch_bounds__(1024) void prep_kernel(const float* __restrict__ key_proj_w,
                                                    const float* __restrict__ ce_w1,
                                                    const float* __restrict__ ce_b1,
                                                    const float* __restrict__ cache_keys,
                                                    const float* __restrict__ ce_w2,
                                                    const float* __restrict__ ce_b2) {
    __shared__ float pooled[BB * HH];     // 16 KB
    __shared__ float qk_s[64];
    __shared__ float qfn[64];
    __shared__ float ceh[2 * CEH];
    __shared__ float sims[16];
    __shared__ float scores[8];
    __shared__ float s_qnorm;
    int tid = threadIdx.x, warp = tid >> 5, lane = tid & 31;

    for (int i = tid; i < BB * HH; i += 1024) {
        float s = 0.f;
        #pragma unroll
        for (int c = 0; c < 8; c++) s += g_pp[c * BB * HH + i];
        pooled[i] = s * (1.0f / SS);
    }
    __syncthreads();

    for (int c = 0; c < 6; c++) {
        int j = warp + 32 * c;
        const float* pl;
        const float* w;
        if (j < 64) {
            pl = pooled + (j / KD) * HH;
            w = key_proj_w + (size_t)(j % KD) * HH;
        } else {
            int jj = j - 64;
            pl = pooled + (jj / CEH) * HH;
            w = ce_w1 + (size_t)(jj % CEH) * HH;
        }
        float s = 0.f;
        for (int k = lane; k < HH; k += 32) s += pl[k] * w[k];
        #pragma unroll
        for (int o = 16; o > 0; o >>= 1) s += __shfl_xor_sync(0xffffffffu, s, o);
        if (lane == 0) {
            if (j < 64) qk_s[j] = s;
            else {
                int jj = j - 64;
                ceh[jj] = fmaxf(s + ce_b1[jj % CEH], 0.f);
            }
        }
    }
    __syncthreads();

    if (warp < 2) {
        float v = qk_s[warp * 32 + lane];
        float s = v * v;
        #pragma unroll
        for (int o = 16; o > 0; o >>= 1) s += __shfl_xor_sync(0xffffffffu, s, o);
        qfn[warp * 32 + lane] = v * (1.0f / fmaxf(sqrtf(s), 1e-8f));
    }
    if (warp >= 8 && warp < 16) {
        int w8 = warp - 8;
        int b = w8 >> 2, r = w8 & 3;
        float s = ceh[b * CEH + lane] * ce_w2[r * CEH + lane]
                + ceh[b * CEH + 32 + lane] * ce_w2[r * CEH + 32 + lane];
        #pragma unroll
        for (int o = 16; o > 0; o >>= 1) s += __shfl_xor_sync(0xffffffffu, s, o);
        if (lane == 0) scores[w8] = s + ce_b2[r];
    }
    __syncthreads();
    if (tid < 32) {
        float s = qfn[tid] * qfn[tid] + qfn[32 + tid] * qfn[32 + tid];
        #pragma unroll
        for (int o = 16; o > 0; o >>= 1) s += __shfl_xor_sync(0xffffffffu, s, o);
        if (tid == 0) s_qnorm = sqrtf(s);
    }
    __syncthreads();
    if (tid < 256) {
        int e = tid >> 4, sub = tid & 15;
        float d = 0.f, n = 0.f;
        #pragma unroll
        for (int i = 0; i < 4; i++) {
            float c = cache_keys[e * 64 + sub * 4 + i];
            d += c * qfn[sub * 4 + i];
            n += c * c;
        }
        #pragma unroll
        for (int o = 8; o > 0; o >>= 1) {
            d += __shfl_xor_sync(0xffffffffu, d, o);
            n += __shfl_xor_sync(0xffffffffu, n, o);
        }
        if (sub == 0)
            sims[e] = d / (fmaxf(sqrtf(n), 1e-8f) * fmaxf(s_qnorm, 1e-8f));
    }
    __syncthreads();
    if (tid == 0) {
        int best = 0;
        float bv = sims[0];
        for (int n = 1; n < NCACHE; n++)
            if (sims[n] > bv) { bv = sims[n]; best = n; }
        g_flags[0] = best;
        g_flags[1] = (bv >= 0.95f) ? 1 : 0;
        int bi = 0;
        float sv = scores[0];
        for (int i = 1; i < 8; i++)
            if (scores[i] > sv) { sv = scores[i]; bi = i; }
        int ri = bi % 4;
        g_flags[2] = ri;
        g_flags[3] = (ri == 0) ? 4 : (ri == 1) ? 12 : (ri == 2) ? 40 : 128;
    }
}

// importance: fused bias+relu+dot over scorer partials (float4, warp per token)
__global__ void imp_kernel(const float* __restrict__ w2,
                           const float* __restrict__ b2,
                           const float* __restrict__ b1,
                           const float* __restrict__ pos) {
    int warp = threadIdx.x >> 5, lane = threadIdx.x & 31;
    int t = blockIdx.x * 4 + warp;
    const float4* p0 = (const float4*)(g_hP + (size_t)t * F1);
    const float4* p1 = (const float4*)(g_hP + (size_t)TT * F1 + (size_t)t * F1);
    const float4* b14 = (const float4*)b1;
    const float4* w24 = (const float4*)w2;
    float s = 0.f;
    #pragma unroll
    for (int it = 0; it < 4; it++) {
        int f = lane + it * 32;              // float4 index, 128 per row
        float4 a = p0[f], b = p1[f], bb = b14[f], w = w24[f];
        s += fmaxf(a.x + b.x + bb.x, 0.f) * w.x;
        s += fmaxf(a.y + b.y + bb.y, 0.f) * w.y;
        s += fmaxf(a.z + b.z + bb.z, 0.f) * w.z;
        s += fmaxf(a.w + b.w + bb.w, 0.f) * w.w;
    }
    #pragma unroll
    for (int o = 16; o > 0; o >>= 1) s += __shfl_xor_sync(0xffffffffu, s, o);
    if (lane == 0) {
        int spos = t % SS;
        float z = s + b2[0] + 0.1f * pos[spos];
        bool edge = (spos == 0 || spos == SS - 1);
        float zc = edge ? ZC_EDGE : ZC_NORM;
        float zs = edge ? ZS_EDGE : ZS_NORM;
        g_crit[t] = (z > zc) ? 1 : 0;
        g_simp[t] = (z < zs) ? 1 : 0;
        if (fabsf(z - zc) < Z_GUARD || fabsf(z - zs) < Z_GUARD) {
            int i = atomicAdd(&g_nflag, 1);
            if (i < 64) g_flist[i] = t;
        }
    }
}

// fp32 recheck of near-threshold tokens + last-block compaction
__global__ __launch_bounds__(256) void recheck_kernel(const float* __restrict__ x,
                                                      const float* __restrict__ w1,
                                                      const float* __restrict__ b1,
                                                      const float* __restrict__ w2,
                                                      const float* __restrict__ b2,
                                                      const float* __restrict__ pos) {
    __shared__ float xs[HH];
    __shared__ float ws[8];
    __shared__ int amLast;
    int tid = threadIdx.x, warp = tid >> 5, lane = tid & 31;

    int nf = g_nflag; if (nf > 64) nf = 64;
    if ((int)blockIdx.x < nf) {
        int t = g_flist[blockIdx.x];
        for (int k = tid; k < HH; k += 256) xs[k] = x[(size_t)t * HH + k];
        __syncthreads();
        float s = 0.f;
        for (int i = 0; i < F1 / 8; i++) {
            int j = warp + i * 8;
            const float* wr = w1 + (size_t)j * HH;
            float d = 0.f;
            for (int k = lane; k < HH; k += 32) d += xs[k] * wr[k];
            #pragma unroll
            for (int o = 16; o > 0; o >>= 1) d += __shfl_xor_sync(0xffffffffu, d, o);
            s += fmaxf(d + b1[j], 0.f) * w2[j];
        }
        if (lane == 0) ws[warp] = s;
        __syncthreads();
        if (tid == 0) {
            float z = b2[0];
            #pragma unroll
            for (int w = 0; w < 8; w++) z += ws[w];
            int spos = t % SS;
            z += 0.1f * pos[spos];
            bool edge = (spos == 0 || spos == SS - 1);
            float zc = edge ? ZC_EDGE : ZC_NORM;
            float zs = edge ? ZS_EDGE : ZS_NORM;
            g_crit[t] = (z > zc) ? 1 : 0;
            g_simp[t] = (z < zs) ? 1 : 0;
        }
    }

    // last block runs deterministic compaction (independent of which block is last)
    __threadfence();
    if (tid == 0) {
        int v = atomicAdd(&g_done, 1);
        amLast = (v == (int)gridDim.x - 1) ? 1 : 0;
    }
    __syncthreads();
    if (amLast) {
        __threadfence();
        if (tid < 32) {
            int cb = 0, nb = 0;
            for (int it = 0; it < TT / 32; it++) {
                int t = it * 32 + tid;
                int c = g_crit[t], s = g_simp[t];
                int nn = !(c || s);
                unsigned cm = __ballot_sync(0xffffffffu, c);
                unsigned nm = __ballot_sync(0xffffffffu, nn);
                unsigned lt = (1u << tid) - 1u;
                if (c) { int p = cb + __popc(cm & lt); g_cidx[p] = t; g_pos[t] = p; }
                if (nn) { int p = nb + __popc(nm & lt); g_nidx[p] = t; g_pos[t] = p; }
                cb += __popc(cm);
                nb += __popc(nm);
            }
            if (tid == 0) {
                g_cnt[0] = cb;
                g_cnt[1] = nb;
                g_done = 0;    // self-reset for next call
            }
        }
    }
}

__device__ __forceinline__ float4 f4add(float4 a, float4 b) {
    return make_float4(a.x + b.x, a.y + b.y, a.z + b.z, a.w + b.w);
}

// final routed epilogue; rank-4 fallback (simple-miss) computed in-place
__global__ __launch_bounds__(256) void final_kernel(const float* __restrict__ x,
                                                    const float* __restrict__ deltas,
                                                    const float* __restrict__ u4,
                                                    const float* __restrict__ v4,
                                                    float* __restrict__ out) {
    int t = blockIdx.x;
    int tid = threadIdx.x;
    int crit = g_crit[t], simp = g_simp[t];
    const float4* x4 = (const float4*)(x + (size_t)t * HH);
    float4* o4 = (float4*)(out + (size_t)t * HH);

    if (crit) {
        const float4* y4 = (const float4*)(g_Y + (size_t)g_pos[t] * HH);
        #pragma unroll
        for (int r = 0; r < 2; r++) {
            int i = r * 256 + tid;
            o4[i] = y4[i];
        }
    } else if (simp) {
        if (g_flags[1]) {
            const float4* d4 = (const float4*)(deltas + (size_t)g_flags[0] * TT * HH + (size_t)t * HH);
            #pragma unroll
            for (int r = 0; r < 2; r++) {
                int i = r * 256 + tid;
                o4[i] = f4add(x4[i], d4[i]);
            }
        } else {
            __shared__ float red[8][4];
            __shared__ float tvals[4];
            int warp = tid >> 5, lane = tid & 31;
            float a0 = 0.f, a1 = 0.f, a2 = 0.f, a3 = 0.f;
            float4 xv_c[2];
            #pragma unroll
            for (int r = 0; r < 2; r++) {
                int i = r * 256 + tid;
                float4 xv = x4[i];
                xv_c[r] = xv;
                const float4 u0 = *(const float4*)(u4 + 0 * HH + i * 4);
                const float4 u1 = *(const float4*)(u4 + 1 * HH + i * 4);
                const float4 u2 = *(const float4*)(u4 + 2 * HH + i * 4);
                const float4 u3 = *(const float4*)(u4 + 3 * HH + i * 4);
                a0 += xv.x * u0.x + xv.y * u0.y + xv.z * u0.z + xv.w * u0.w;
                a1 += xv.x * u1.x + xv.y * u1.y + xv.z * u1.z + xv.w * u1.w;
                a2 += xv.x * u2.x + xv.y * u2.y + xv.z * u2.z + xv.w * u2.w;
                a3 += xv.x * u3.x + xv.y * u3.y + xv.z * u3.z + xv.w * u3.w;
            }
            #pragma unroll
            for (int o = 16; o > 0; o >>= 1) {
                a0 += __shfl_xor_sync(0xffffffffu, a0, o);
                a1 += __shfl_xor_sync(0xffffffffu, a1, o);
                a2 += __shfl_xor_sync(0xffffffffu, a2, o);
                a3 += __shfl_xor_sync(0xffffffffu, a3, o);
            }
            if (lane == 0) {
                red[warp][0] = a0; red[warp][1] = a1;
                red[warp][2] = a2; red[warp][3] = a3;
            }
            __syncthreads();
            if (tid < 4) {
                float s = 0.f;
                #pragma unroll
                for (int w = 0; w < 8; w++) s += red[w][tid];
                tvals[tid] = s;
            }
            __syncthreads();
            float t0 = tvals[0], t1 = tvals[1], t2 = tvals[2], t3 = tvals[3];
            const float4* v44 = (const float4*)v4;
            #pragma unroll
            for (int r = 0; r < 2; r++) {
                int i = r * 256 + tid;
                int h = i * 4;
                float4 xv = xv_c[r];
                float lr[4];
                #pragma unroll
                for (int j = 0; j < 4; j++) {
                    float4 vr = v44[h + j];
                    lr[j] = t0 * vr.x + t1 * vr.y + t2 * vr.z + t3 * vr.w;
                }
                o4[i] = make_float4(xv.x + lr[0], xv.y + lr[1], xv.z + lr[2], xv.w + lr[3]);
            }
        }
    } else {
        const float4* l4 = (const float4*)(g_Lsel + (size_t)g_pos[t] * HH);
        #pragma unroll
        for (int r = 0; r < 2; r++) {
            int i = r * 256 + tid;
            o4[i] = f4add(x4[i], l4[i]);
        }
    }
}

// =================== launch (two-stream graph) ===================
extern "C" void kernel_launch(void* const* d_in, const int* in_sizes, int n_in,
                              void* d_out, int out_size) {
    const float* x          = (const float*)d_in[0];
    const float* scorer_w1  = (const float*)d_in[1];
    const float* scorer_b1  = (const float*)d_in[2];
    const float* scorer_w2  = (const float*)d_in[3];
    const float* scorer_b2  = (const float*)d_in[4];
    const float* pos_imp    = (const float*)d_in[5];
    const float* key_proj_w = (const float*)d_in[6];
    const float* cache_keys = (const float*)d_in[7];
    const float* cache_del  = (const float*)d_in[8];
    const float* ce_w1      = (const float*)d_in[9];
    const float* ce_b1      = (const float*)d_in[10];
    const float* ce_w2      = (const float*)d_in[11];
    const float* ce_b2      = (const float*)d_in[12];
    const float* u4   = (const float*)d_in[13];
    const float* v4   = (const float*)d_in[14];
    const float* u12  = (const float*)d_in[15];
    const float* v12  = (const float*)d_in[16];
    const float* u40  = (const float*)d_in[17];
    const float* v40  = (const float*)d_in[18];
    const float* u128 = (const float*)d_in[19];
    const float* v128 = (const float*)d_in[20];
    const float* layer_w = (const float*)d_in[21];
    const float* layer_b = (const float*)d_in[22];
    float* out = (float*)d_out;

    float* d_hP; cudaGetSymbolAddress((void**)&d_hP, g_hP);
    float* d_Y;  cudaGetSymbolAddress((void**)&d_Y, g_Y);

    // fork stream + events (host-side objects; created on the few real calls only —
    // graph replays do not re-execute host code)
    cudaStream_t s2;
    cudaStreamCreateWithFlags(&s2, cudaStreamNonBlocking);
    cudaEvent_t evFork, evCompact, evSide;
    cudaEventCreateWithFlags(&evFork,    cudaEventDisableTiming);
    cudaEventCreateWithFlags(&evCompact, cudaEventDisableTiming);
    cudaEventCreateWithFlags(&evSide,    cudaEventDisableTiming);

    // ---- fork ----
    cudaEventRecord(evFork, 0);
    cudaStreamWaitEvent(s2, evFork, 0);

    // stream B (side): pooled stats + selection flags
    pool_part<<<dim3(16, 8), 256, 0, s2>>>(x);
    prep_kernel<<<1, 1024, 0, s2>>>(key_proj_w, ce_w1, ce_b1, cache_keys, ce_w2, ce_b2);

    // stream A (main): scorer -> imp -> recheck(+compact)
    g_scorer<<<dim3(16, 4, 2), 256, SMEM_BF>>>(x, scorer_w1, d_hP);
    imp_kernel<<<512, 128>>>(scorer_w2, scorer_b2, scorer_b1, pos_imp);
    recheck_kernel<<<64, 256>>>(x, scorer_w1, scorer_b1, scorer_w2, scorer_b2, pos_imp);
    cudaEventRecord(evCompact, 0);

    // stream A continues: layer GEMM on critical tokens
    g_layer<<<dim3(16, 16), 256, SMEM_BF>>>(x, layer_w, layer_b, d_Y);

    // stream B: tsel chain (needs compact from A + flags from its own prep)
    cudaStreamWaitEvent(s2, evCompact, 0);
    g_tsel<<<dim3(16, 1, NSPLIT_T), 256, SMEM_BF, s2>>>(x, u4, u12, u40, u128);
    tsel_reduce<<<TT * 128 / 256, 256, 0, s2>>>();
    g_lsel<<<dim3(16, 16), 256, SMEM_BF, s2>>>(v4, v12, v40, v128);
    cudaEventRecord(evSide, s2);

    // ---- join ----
    cudaStreamWaitEvent(0, evSide, 0);
    final_kernel<<<TT, 256>>>(x, cache_del, u4, v4, out);
}